// round 10
// baseline (speedup 1.0000x reference)
#include <cuda_runtime.h>
#include <math.h>

#define B_   128
#define T_   512
#define I_   64
#define H_   512
#define L_   64
#define DEC_ 100

typedef unsigned long long ull;

#define NBLK 128
#define NTHR 256
#define NBAR 715           // 1 + 512 + 1 + 1 + 200

// ---------------- device globals ----------------
__device__ unsigned g_bar[1024];
__device__ float g_h[2][B_ * H_];
__device__ float g_z[B_ * L_];
__device__ float g_x[B_ * L_];

__device__ __forceinline__ float sigf(float v) { return 1.0f / (1.0f + expf(-v)); }

__device__ __forceinline__ void ffma2(ull& d, ull a, ull b) {
    asm("fma.rn.f32x2 %0, %1, %2, %0;" : "+l"(d) : "l"(a), "l"(b));
}

// ---------------- software grid barrier (128 co-resident blocks) ----------------
__device__ __forceinline__ void grid_bar(int idx, int tid, int bid)
{
    __threadfence();
    __syncthreads();
    if (tid == 0) {
        atomicAdd(&g_bar[idx], 1u);
        volatile unsigned* p = &g_bar[idx];
        while (*p < (unsigned)NBLK) {}
        __threadfence();
        if (bid == 0 && idx > 0) atomicExch(&g_bar[idx - 1], 0u);
    }
    __syncthreads();
}

// group-local barrier (4 warps = 128 threads), ids 1 and 2
__device__ __forceinline__ void bar_group(int g)
{
    asm volatile("bar.sync %0, %1;" :: "r"(g + 1), "r"(128) : "memory");
}

// ---------------- smem layout (floats) ----------------
// Ws  : [32 n][580]  natural [n][k] weight rows (k 0..63 = Wih, 64..575 = Whh)
// As0 : [64 m][64 k] chunk buffer group 0 (column-rotated)
// As1 : same, group 1
// Xs  : [64][33] split-K partials (dedicated — overlaying As1 races)
// bsum: [32]
#define WS_STR   580
#define WS_OFF   0
#define AS0_OFF  (32 * WS_STR)                 // 18560
#define AS1_OFF  (AS0_OFF + 4096)              // 22656
#define XS_OFF   (AS1_OFF + 4096)              // 26752
#define BSUM_OFF (XS_OFF + 64 * 33)            // 28864
#define SMEM_FLTS (BSUM_OFF + 32)
#define SMEM_BYTES (SMEM_FLTS * 4)

// ---------------- resident weight loader (natural [n][k] layout) ----------------
__device__ __forceinline__ void load_weights(float* Ws, float* bsum,
    const float* __restrict__ Wih, const float* __restrict__ Whh,
    const float* __restrict__ bih, const float* __restrict__ bhh,
    int j0, int tid)
{
    __syncthreads();
    // Wih: 32 rows x 64 k
    for (int q = tid; q < 32 * 16; q += NTHR) {
        int r = q >> 4, k4 = q & 15;
        int row = (r >> 3) * H_ + j0 + (r & 7);
        *(float4*)(Ws + r * WS_STR + k4 * 4) = *(const float4*)(Wih + row * I_ + k4 * 4);
    }
    // Whh: 32 rows x 512 k -> cols 64..575
    for (int q = tid; q < 32 * 128; q += NTHR) {
        int r = q >> 7, k4 = q & 127;
        int row = (r >> 3) * H_ + j0 + (r & 7);
        *(float4*)(Ws + r * WS_STR + 64 + k4 * 4) = *(const float4*)(Whh + row * H_ + k4 * 4);
    }
    if (tid < 32) {
        int g = tid >> 3, jj = tid & 7;
        bsum[tid] = bih[g * H_ + j0 + jj] + bhh[g * H_ + j0 + jj];
    }
    __syncthreads();
}

// chunk t source: t==0 -> x (K=64), t>=1 -> h (K offset (t-1)*64)
__device__ __forceinline__ void chunk_src(int t,
    const float* xsrc, int xld, const float* hsrc,
    const float*& Ap, int& lda, int& koff)
{
    if (t == 0) { Ap = xsrc; lda = xld; koff = 0; }
    else        { Ap = hsrc; lda = H_;  koff = (t - 1) * 64; }
}

// ---------------- fused GEMM + cell update, split-K across 2 warp groups ----------------
// Tile: 64 batch x 32 gate-cols. Thread (ty,tx) in group g: microtile 4m x 4gates,
// m = 4*ty+i, gate col r = tx + 8*gate (jj = tx). f32x2 pairs along K, LDS.128 loads.
__device__ __forceinline__ void gemm_cell_step(
    const float* __restrict__ xsrc, int xld,
    const float* __restrict__ hsrc,
    float* __restrict__ hdst,
    const float* Ws, float* As0, float* As1, float* Xs, const float* bsum,
    float* c_reg, int m0, int j0, int tid)
{
    const int w    = tid >> 5;
    const int g    = w >> 2;          // 0: chunks 0..4, 1: chunks 5..8
    const int gtid = tid & 127;
    const int tx   = gtid & 7;
    const int ty   = gtid >> 3;       // 0..15
    float* Af = g ? As1 : As0;
    const int cbeg = g ? 5 : 0;
    const int cend = g ? 9 : 5;

    ull acc[4][4];
#pragma unroll
    for (int i = 0; i < 4; ++i)
#pragma unroll
        for (int j = 0; j < 4; ++j) acc[i][j] = 0ull;

    float4 st[8];
    {   // prefetch first chunk
        const float* Ap; int lda, koff;
        chunk_src(cbeg, xsrc, xld, hsrc, Ap, lda, koff);
#pragma unroll
        for (int i = 0; i < 8; ++i) {
            int idx = gtid + i * 128;
            int m = idx >> 4, k4 = idx & 15;
            st[i] = *(const float4*)(Ap + (m0 + m) * lda + koff + k4 * 4);
        }
    }

    const int colbase = 8 * (ty & 7);
    const float* b0p = Ws + (tx +  0) * WS_STR;
    const float* b1p = Ws + (tx +  8) * WS_STR;
    const float* b2p = Ws + (tx + 16) * WS_STR;
    const float* b3p = Ws + (tx + 24) * WS_STR;

    for (int t = cbeg; t < cend; ++t) {
        bar_group(g);                      // previous chunk's compute done
        // store staged chunk (column-rotated by m>>2 to spread read banks)
#pragma unroll
        for (int i = 0; i < 8; ++i) {
            int idx = gtid + i * 128;
            int m = idx >> 4, k4 = idx & 15;
            int col = (k4 * 4 + 8 * ((m >> 2) & 7)) & 63;
            *(float4*)(Af + m * 64 + col) = st[i];
        }
        bar_group(g);
        if (t + 1 < cend) {                // prefetch next chunk
            const float* Ap; int lda, koff;
            chunk_src(t + 1, xsrc, xld, hsrc, Ap, lda, koff);
#pragma unroll
            for (int i = 0; i < 8; ++i) {
                int idx = gtid + i * 128;
                int m = idx >> 4, k4 = idx & 15;
                st[i] = *(const float4*)(Ap + (m0 + m) * lda + koff + k4 * 4);
            }
        }
        const int kb = t * 64;
        const float* a0p = Af + (4 * ty + 0) * 64;
        const float* a1p = Af + (4 * ty + 1) * 64;
        const float* a2p = Af + (4 * ty + 2) * 64;
        const float* a3p = Af + (4 * ty + 3) * 64;
#pragma unroll 4
        for (int kq = 0; kq < 16; ++kq) {      // 4 k per iter, LDS.128
            int col = (4 * kq + colbase) & 63;
            ulonglong2 A0 = *(const ulonglong2*)(a0p + col);
            ulonglong2 A1 = *(const ulonglong2*)(a1p + col);
            ulonglong2 A2 = *(const ulonglong2*)(a2p + col);
            ulonglong2 A3 = *(const ulonglong2*)(a3p + col);
            ulonglong2 B0 = *(const ulonglong2*)(b0p + kb + 4 * kq);
            ulonglong2 B1 = *(const ulonglong2*)(b1p + kb + 4 * kq);
            ulonglong2 B2 = *(const ulonglong2*)(b2p + kb + 4 * kq);
            ulonglong2 B3 = *(const ulonglong2*)(b3p + kb + 4 * kq);
            ffma2(acc[0][0], A0.x, B0.x); ffma2(acc[0][1], A0.x, B1.x);
            ffma2(acc[0][2], A0.x, B2.x); ffma2(acc[0][3], A0.x, B3.x);
            ffma2(acc[1][0], A1.x, B0.x); ffma2(acc[1][1], A1.x, B1.x);
            ffma2(acc[1][2], A1.x, B2.x); ffma2(acc[1][3], A1.x, B3.x);
            ffma2(acc[2][0], A2.x, B0.x); ffma2(acc[2][1], A2.x, B1.x);
            ffma2(acc[2][2], A2.x, B2.x); ffma2(acc[2][3], A2.x, B3.x);
            ffma2(acc[3][0], A3.x, B0.x); ffma2(acc[3][1], A3.x, B1.x);
            ffma2(acc[3][2], A3.x, B2.x); ffma2(acc[3][3], A3.x, B3.x);
            ffma2(acc[0][0], A0.y, B0.y); ffma2(acc[0][1], A0.y, B1.y);
            ffma2(acc[0][2], A0.y, B2.y); ffma2(acc[0][3], A0.y, B3.y);
            ffma2(acc[1][0], A1.y, B0.y); ffma2(acc[1][1], A1.y, B1.y);
            ffma2(acc[1][2], A1.y, B2.y); ffma2(acc[1][3], A1.y, B3.y);
            ffma2(acc[2][0], A2.y, B0.y); ffma2(acc[2][1], A2.y, B1.y);
            ffma2(acc[2][2], A2.y, B2.y); ffma2(acc[2][3], A2.y, B3.y);
            ffma2(acc[3][0], A3.y, B0.y); ffma2(acc[3][1], A3.y, B1.y);
            ffma2(acc[3][2], A3.y, B2.y); ffma2(acc[3][3], A3.y, B3.y);
        }
    }

    // epilogue: lo+hi horizontal reduce
    float s[4][4];
#pragma unroll
    for (int i = 0; i < 4; ++i)
#pragma unroll
        for (int j = 0; j < 4; ++j) {
            ull v = acc[i][j];
            s[i][j] = __uint_as_float((unsigned)(v & 0xffffffffull))
                    + __uint_as_float((unsigned)(v >> 32));
        }

    if (g == 1) {   // publish group-1 partials
#pragma unroll
        for (int i = 0; i < 4; ++i)
#pragma unroll
            for (int j = 0; j < 4; ++j)
                Xs[(4 * ty + i) * 33 + tx + 8 * j] = s[i][j];
    }
    __syncthreads();
    if (g == 0) {   // combine + cell update, c in registers
#pragma unroll
        for (int i = 0; i < 4; ++i) {
            int m = 4 * ty + i;
            float gi = s[i][0] + Xs[m * 33 + tx]      + bsum[tx];
            float gf = s[i][1] + Xs[m * 33 + tx + 8]  + bsum[8 + tx];
            float gg = s[i][2] + Xs[m * 33 + tx + 16] + bsum[16 + tx];
            float go = s[i][3] + Xs[m * 33 + tx + 24] + bsum[24 + tx];
            float cn = sigf(gf) * c_reg[i] + sigf(gi) * tanhf(gg);
            float hn = sigf(go) * tanhf(cn);
            c_reg[i] = cn;
            hdst[(m0 + m) * H_ + j0 + tx] = hn;
        }
    }
    __syncthreads();
}

// ---------------- the megakernel ----------------
__global__ void __launch_bounds__(NTHR, 1)
vae_mega(const float* __restrict__ seq,  const float* __restrict__ eps,
         const float* __restrict__ Wih_e, const float* __restrict__ Whh_e,
         const float* __restrict__ bih_e, const float* __restrict__ bhh_e,
         const float* __restrict__ Wm, const float* __restrict__ bm,
         const float* __restrict__ Wv, const float* __restrict__ bv,
         const float* __restrict__ Wi, const float* __restrict__ bi,
         const float* __restrict__ Wih_d, const float* __restrict__ Whh_d,
         const float* __restrict__ bih_d, const float* __restrict__ bhh_d,
         const float* __restrict__ Wo, const float* __restrict__ bo,
         float* __restrict__ out_xhat, float* __restrict__ out_mean,
         float* __restrict__ out_lv)
{
    extern __shared__ float smem[];
    float* Ws   = smem + WS_OFF;
    float* As0  = smem + AS0_OFF;
    float* As1  = smem + AS1_OFF;
    float* Xs   = smem + XS_OFF;
    float* bsum = smem + BSUM_OFF;

    const int tid = threadIdx.x;
    const int bid = blockIdx.x;
    const int j0  = (bid >> 1) * 8;
    const int m0  = (bid & 1) * 64;
    const int gwarp = bid * 8 + (tid >> 5);   // 0..1023
    const int lane  = tid & 31;

    int barid = 0;
    if (bid == 0 && tid == 0) atomicExch(&g_bar[NBAR - 1], 0u);

    float c_reg[4];

    // ===== encoder =====
    load_weights(Ws, bsum, Wih_e, Whh_e, bih_e, bhh_e, j0, tid);
#pragma unroll
    for (int q = 0; q < 2; ++q) {
        int idx = q * (NBLK * NTHR) + bid * NTHR + tid;
        if (idx < B_ * H_) g_h[0][idx] = 0.0f;
    }
#pragma unroll
    for (int i = 0; i < 4; ++i) c_reg[i] = 0.0f;
    grid_bar(barid++, tid, bid);

    for (int t = 0; t < T_; ++t) {
        gemm_cell_step(seq + t * I_, T_ * I_,
                       g_h[t & 1], g_h[(t + 1) & 1],
                       Ws, As0, As1, Xs, bsum, c_reg, m0, j0, tid);
        grid_bar(barid++, tid, bid);
    }
    // h_n in g_h[0]

    // ===== VAE =====
    {
        const float* hn = g_h[0];
        for (int o = 0; o < 8; ++o) {
            int idx = gwarp * 8 + o;             // 0..8191
            int b = idx >> 6, l = idx & 63;
            const float* hb = hn + b * H_;
            const float* wm = Wm + l * H_;
            const float* wv = Wv + l * H_;
            float sm = 0.0f, sv = 0.0f;
#pragma unroll 4
            for (int k = lane; k < H_; k += 32) {
                float hv = hb[k];
                sm += hv * wm[k];
                sv += hv * wv[k];
            }
#pragma unroll
            for (int off = 16; off > 0; off >>= 1) {
                sm += __shfl_down_sync(0xffffffffu, sm, off);
                sv += __shfl_down_sync(0xffffffffu, sv, off);
            }
            if (lane == 0) {
                sm += bm[l];
                sv += bv[l];
                out_mean[b * L_ + l] = sm;
                out_lv  [b * L_ + l] = sv;
                g_z[b * L_ + l] = sm + eps[b * L_ + l] * expf(0.5f * sv);
            }
        }
    }
    grid_bar(barid++, tid, bid);

    // ===== decoder init =====
    load_weights(Ws, bsum, Wih_d, Whh_d, bih_d, bhh_d, j0, tid);
    {
        int gt = bid * NTHR + tid;               // 0..32767
#pragma unroll
        for (int q = 0; q < 2; ++q) {
            int idx = q * 32768 + gt;            // 0..65535
            int b = idx >> 9, j = idx & 511;
            const float* zb = g_z + b * L_;
            const float* wr = Wi + j * L_;
            float s = bi[j];
#pragma unroll 16
            for (int k = 0; k < L_; ++k) s += zb[k] * wr[k];
            g_h[0][b * H_ + j] = s;
        }
        if (gt < B_ * L_) g_x[gt] = 0.0f;
#pragma unroll
        for (int i = 0; i < 4; ++i) c_reg[i] = 0.0f;
    }
    grid_bar(barid++, tid, bid);

    // ===== decoder loop =====
    for (int s = 0; s < DEC_; ++s) {
        gemm_cell_step(g_x, L_,
                       g_h[s & 1], g_h[(s + 1) & 1],
                       Ws, As0, As1, Xs, bsum, c_reg, m0, j0, tid);
        grid_bar(barid++, tid, bid);

        const float* hcur = g_h[(s + 1) & 1];
        for (int o = 0; o < 8; ++o) {
            int idx = gwarp * 8 + o;             // 0..8191
            int b = idx >> 6, i = idx & 63;
            const float* hb = hcur + b * H_;
            const float* wr = Wo + i * H_;
            float sum = 0.0f;
#pragma unroll 4
            for (int k = lane; k < H_; k += 32) sum += hb[k] * wr[k];
#pragma unroll
            for (int off = 16; off > 0; off >>= 1)
                sum += __shfl_down_sync(0xffffffffu, sum, off);
            if (lane == 0) {
                float v = sum + bo[i];
                g_x[b * I_ + i] = v;
                out_xhat[(b * DEC_ + s) * I_ + i] = v;
            }
        }
        grid_bar(barid++, tid, bid);
    }
}

// ---------------- launch ----------------
extern "C" void kernel_launch(void* const* d_in, const int* in_sizes, int n_in,
                              void* d_out, int out_size)
{
    (void)in_sizes; (void)n_in; (void)out_size;

    const float* seq    = (const float*)d_in[0];
    const float* eps    = (const float*)d_in[2];
    const float* Wih_e  = (const float*)d_in[3];
    const float* Whh_e  = (const float*)d_in[4];
    const float* bih_e  = (const float*)d_in[5];
    const float* bhh_e  = (const float*)d_in[6];
    const float* Wm     = (const float*)d_in[7];
    const float* bm     = (const float*)d_in[8];
    const float* Wv     = (const float*)d_in[9];
    const float* bv     = (const float*)d_in[10];
    const float* Wi     = (const float*)d_in[11];
    const float* bi     = (const float*)d_in[12];
    const float* Wih_d  = (const float*)d_in[13];
    const float* Whh_d  = (const float*)d_in[14];
    const float* bih_d  = (const float*)d_in[15];
    const float* bhh_d  = (const float*)d_in[16];
    const float* Wo     = (const float*)d_in[17];
    const float* bo     = (const float*)d_in[18];

    float* out      = (float*)d_out;
    float* out_xhat = out;
    float* out_mean = out + B_ * DEC_ * I_;
    float* out_lv   = out_mean + B_ * L_;

    cudaFuncSetAttribute(vae_mega, cudaFuncAttributeMaxDynamicSharedMemorySize,
                         SMEM_BYTES);

    vae_mega<<<NBLK, NTHR, SMEM_BYTES>>>(
        seq, eps,
        Wih_e, Whh_e, bih_e, bhh_e,
        Wm, bm, Wv, bv, Wi, bi,
        Wih_d, Whh_d, bih_d, bhh_d,
        Wo, bo,
        out_xhat, out_mean, out_lv);
}

// round 11
// speedup vs baseline: 1.0447x; 1.0447x over previous
#include <cuda_runtime.h>
#include <math.h>

#define B_   128
#define T_   512
#define I_   64
#define H_   512
#define L_   64
#define DEC_ 100

typedef unsigned long long ull;

#define NBLK   128
#define NTHR   384
#define NWARP  12
#define NBAR   715           // 1 + 512 + 1 + 1 + 200

// ---------------- device globals ----------------
__device__ unsigned g_bar[1024];
__device__ __align__(16) float g_h[2][B_ * H_];
__device__ __align__(16) float g_z[B_ * L_];
__device__ __align__(16) float g_x[B_ * L_];

__device__ __forceinline__ float sigf(float v) { return 1.0f / (1.0f + expf(-v)); }

__device__ __forceinline__ void ffma2(ull& d, ull a, ull b) {
    asm("fma.rn.f32x2 %0, %1, %2, %0;" : "+l"(d) : "l"(a), "l"(b));
}

__device__ __forceinline__ unsigned smem_u32(const void* p) {
    return (unsigned)__cvta_generic_to_shared(p);
}
__device__ __forceinline__ void cp_async16(unsigned dst, const void* src) {
    asm volatile("cp.async.cg.shared.global [%0], [%1], 16;" :: "r"(dst), "l"(src));
}
#define CP_COMMIT() asm volatile("cp.async.commit_group;" ::: "memory")
#define CP_WAIT0()  asm volatile("cp.async.wait_group 0;"  ::: "memory")

// ---------------- software grid barrier (128 co-resident blocks) ----------------
__device__ __forceinline__ void grid_bar(int idx, int tid, int bid)
{
    __threadfence();
    __syncthreads();
    if (tid == 0) {
        atomicAdd(&g_bar[idx], 1u);
        volatile unsigned* p = &g_bar[idx];
        while (*p < (unsigned)NBLK) {}
        __threadfence();
        if (bid == 0 && idx > 0) atomicExch(&g_bar[idx - 1], 0u);
    }
    __syncthreads();
}

// group-local barrier (4 warps = 128 threads); named barrier ids 1..3
__device__ __forceinline__ void bar_group(int g)
{
    asm volatile("bar.sync %0, %1;" :: "r"(g + 1), "r"(128) : "memory");
}

// ---------------- smem layout (floats) ----------------
// Ws  : [32 n][580]  natural [n][k] weight rows (k 0..63 = Wih, 64..575 = Whh)
// As  : 3 groups x 2 buffers x [64 m][64 k] (column-rotated), cp.async filled
// Xs  : 2 x [64][33] split-K partials (groups 1,2 publish)
// bsum: [32]
#define WS_STR   580
#define WS_OFF   0
#define AS_OFF   (32 * WS_STR)                  // 18560
#define XS_OFF   (AS_OFF + 3 * 2 * 4096)        // 43136
#define BSUM_OFF (XS_OFF + 2 * 64 * 33)         // 47360
#define SMEM_FLTS (BSUM_OFF + 32)               // 47392
#define SMEM_BYTES (SMEM_FLTS * 4)              // 189568

// ---------------- resident weight loader (natural [n][k] layout) ----------------
__device__ __forceinline__ void load_weights(float* Ws, float* bsum,
    const float* __restrict__ Wih, const float* __restrict__ Whh,
    const float* __restrict__ bih, const float* __restrict__ bhh,
    int j0, int tid)
{
    __syncthreads();
    for (int q = tid; q < 32 * 16; q += NTHR) {
        int r = q >> 4, k4 = q & 15;
        int row = (r >> 3) * H_ + j0 + (r & 7);
        *(float4*)(Ws + r * WS_STR + k4 * 4) = *(const float4*)(Wih + row * I_ + k4 * 4);
    }
    for (int q = tid; q < 32 * 128; q += NTHR) {
        int r = q >> 7, k4 = q & 127;
        int row = (r >> 3) * H_ + j0 + (r & 7);
        *(float4*)(Ws + r * WS_STR + 64 + k4 * 4) = *(const float4*)(Whh + row * H_ + k4 * 4);
    }
    if (tid < 32) {
        int g = tid >> 3, jj = tid & 7;
        bsum[tid] = bih[g * H_ + j0 + jj] + bhh[g * H_ + j0 + jj];
    }
    __syncthreads();
}

// chunk c source: c==0 -> x (K=64), c>=1 -> h (K offset (c-1)*64)
__device__ __forceinline__ void chunk_src(int c,
    const float* xsrc, int xld, const float* hsrc,
    const float*& Ap, int& lda, int& koff)
{
    if (c == 0) { Ap = xsrc; lda = xld; koff = 0; }
    else        { Ap = hsrc; lda = H_;  koff = (c - 1) * 64; }
}

// issue cp.async fill of chunk c into dstbuf (column-rotated layout)
__device__ __forceinline__ void issue_chunk(int c,
    const float* xsrc, int xld, const float* hsrc,
    float* dstbuf, int m0, int gtid)
{
    const float* Ap; int lda, koff;
    chunk_src(c, xsrc, xld, hsrc, Ap, lda, koff);
#pragma unroll
    for (int i = 0; i < 8; ++i) {
        int idx = gtid + i * 128;
        int m = idx >> 4, k4 = idx & 15;
        int col = (k4 * 4 + 8 * ((m >> 2) & 7)) & 63;
        cp_async16(smem_u32(dstbuf + m * 64 + col),
                   Ap + (m0 + m) * lda + koff + k4 * 4);
    }
    CP_COMMIT();
}

// ---------------- fused GEMM + cell update, 3-way split-K ----------------
// Tile: 64 batch x 32 gate-cols. Thread (ty,tx) in group g: microtile 4m x 4gates.
// Group g handles chunks 3g..3g+2 (K=192 each). f32x2 pairs along K, LDS.128.
__device__ __forceinline__ void gemm_cell_step(
    const float* __restrict__ xsrc, int xld,
    const float* __restrict__ hsrc,
    float* __restrict__ hdst,
    const float* Ws, float* As, float* Xs, const float* bsum,
    float* c_reg, int m0, int j0, int tid)
{
    const int g    = tid >> 7;        // warp-group 0..2
    const int gtid = tid & 127;
    const int tx   = gtid & 7;
    const int ty   = gtid >> 3;       // 0..15
    float* Asg = As + g * (2 * 4096);
    const int cbeg = 3 * g;

    ull acc[4][4];
#pragma unroll
    for (int i = 0; i < 4; ++i)
#pragma unroll
        for (int j = 0; j < 4; ++j) acc[i][j] = 0ull;

    const int colbase = 8 * (ty & 7);
    const float* b0p = Ws + (tx +  0) * WS_STR;
    const float* b1p = Ws + (tx +  8) * WS_STR;
    const float* b2p = Ws + (tx + 16) * WS_STR;
    const float* b3p = Ws + (tx + 24) * WS_STR;

    issue_chunk(cbeg, xsrc, xld, hsrc, Asg, m0, gtid);

#pragma unroll
    for (int ci = 0; ci < 3; ++ci) {
        CP_WAIT0();                   // my slice of chunk ci landed
        bar_group(g);                 // whole group's slice landed; prev buf free
        if (ci < 2)
            issue_chunk(cbeg + ci + 1, xsrc, xld, hsrc,
                        Asg + ((ci + 1) & 1) * 4096, m0, gtid);

        const float* Af = Asg + (ci & 1) * 4096;
        const int kb = (cbeg + ci) * 64;
        const float* a0p = Af + (4 * ty + 0) * 64;
        const float* a1p = Af + (4 * ty + 1) * 64;
        const float* a2p = Af + (4 * ty + 2) * 64;
        const float* a3p = Af + (4 * ty + 3) * 64;
#pragma unroll 4
        for (int kq = 0; kq < 16; ++kq) {      // 4 k per iter, LDS.128
            int col = (4 * kq + colbase) & 63;
            ulonglong2 A0 = *(const ulonglong2*)(a0p + col);
            ulonglong2 A1 = *(const ulonglong2*)(a1p + col);
            ulonglong2 A2 = *(const ulonglong2*)(a2p + col);
            ulonglong2 A3 = *(const ulonglong2*)(a3p + col);
            ulonglong2 B0 = *(const ulonglong2*)(b0p + kb + 4 * kq);
            ulonglong2 B1 = *(const ulonglong2*)(b1p + kb + 4 * kq);
            ulonglong2 B2 = *(const ulonglong2*)(b2p + kb + 4 * kq);
            ulonglong2 B3 = *(const ulonglong2*)(b3p + kb + 4 * kq);
            ffma2(acc[0][0], A0.x, B0.x); ffma2(acc[0][1], A0.x, B1.x);
            ffma2(acc[0][2], A0.x, B2.x); ffma2(acc[0][3], A0.x, B3.x);
            ffma2(acc[1][0], A1.x, B0.x); ffma2(acc[1][1], A1.x, B1.x);
            ffma2(acc[1][2], A1.x, B2.x); ffma2(acc[1][3], A1.x, B3.x);
            ffma2(acc[2][0], A2.x, B0.x); ffma2(acc[2][1], A2.x, B1.x);
            ffma2(acc[2][2], A2.x, B2.x); ffma2(acc[2][3], A2.x, B3.x);
            ffma2(acc[3][0], A3.x, B0.x); ffma2(acc[3][1], A3.x, B1.x);
            ffma2(acc[3][2], A3.x, B2.x); ffma2(acc[3][3], A3.x, B3.x);
            ffma2(acc[0][0], A0.y, B0.y); ffma2(acc[0][1], A0.y, B1.y);
            ffma2(acc[0][2], A0.y, B2.y); ffma2(acc[0][3], A0.y, B3.y);
            ffma2(acc[1][0], A1.y, B0.y); ffma2(acc[1][1], A1.y, B1.y);
            ffma2(acc[1][2], A1.y, B2.y); ffma2(acc[1][3], A1.y, B3.y);
            ffma2(acc[2][0], A2.y, B0.y); ffma2(acc[2][1], A2.y, B1.y);
            ffma2(acc[2][2], A2.y, B2.y); ffma2(acc[2][3], A2.y, B3.y);
            ffma2(acc[3][0], A3.y, B0.y); ffma2(acc[3][1], A3.y, B1.y);
            ffma2(acc[3][2], A3.y, B2.y); ffma2(acc[3][3], A3.y, B3.y);
        }
    }

    // epilogue: lo+hi horizontal reduce
    float s[4][4];
#pragma unroll
    for (int i = 0; i < 4; ++i)
#pragma unroll
        for (int j = 0; j < 4; ++j) {
            ull v = acc[i][j];
            s[i][j] = __uint_as_float((unsigned)(v & 0xffffffffull))
                    + __uint_as_float((unsigned)(v >> 32));
        }

    if (g > 0) {   // groups 1,2 publish partials to dedicated regions
        float* Xg = Xs + (g - 1) * (64 * 33);
#pragma unroll
        for (int i = 0; i < 4; ++i)
#pragma unroll
            for (int j = 0; j < 4; ++j)
                Xg[(4 * ty + i) * 33 + tx + 8 * j] = s[i][j];
    }
    __syncthreads();
    if (g == 0) {  // combine + cell update, c in registers
#pragma unroll
        for (int i = 0; i < 4; ++i) {
            int m = 4 * ty + i;
            float gi = s[i][0] + Xs[m * 33 + tx]            + Xs[64*33 + m * 33 + tx]            + bsum[tx];
            float gf = s[i][1] + Xs[m * 33 + tx + 8]        + Xs[64*33 + m * 33 + tx + 8]        + bsum[8 + tx];
            float gg = s[i][2] + Xs[m * 33 + tx + 16]       + Xs[64*33 + m * 33 + tx + 16]       + bsum[16 + tx];
            float go = s[i][3] + Xs[m * 33 + tx + 24]       + Xs[64*33 + m * 33 + tx + 24]       + bsum[24 + tx];
            float cn = sigf(gf) * c_reg[i] + sigf(gi) * tanhf(gg);
            float hn = sigf(go) * tanhf(cn);
            c_reg[i] = cn;
            hdst[(m0 + m) * H_ + j0 + tx] = hn;
        }
    }
    __syncthreads();
}

// ---------------- the megakernel ----------------
__global__ void __launch_bounds__(NTHR, 1)
vae_mega(const float* __restrict__ seq,  const float* __restrict__ eps,
         const float* __restrict__ Wih_e, const float* __restrict__ Whh_e,
         const float* __restrict__ bih_e, const float* __restrict__ bhh_e,
         const float* __restrict__ Wm, const float* __restrict__ bm,
         const float* __restrict__ Wv, const float* __restrict__ bv,
         const float* __restrict__ Wi, const float* __restrict__ bi,
         const float* __restrict__ Wih_d, const float* __restrict__ Whh_d,
         const float* __restrict__ bih_d, const float* __restrict__ bhh_d,
         const float* __restrict__ Wo, const float* __restrict__ bo,
         float* __restrict__ out_xhat, float* __restrict__ out_mean,
         float* __restrict__ out_lv)
{
    extern __shared__ float smem[];
    float* Ws   = smem + WS_OFF;
    float* As   = smem + AS_OFF;
    float* Xs   = smem + XS_OFF;
    float* bsum = smem + BSUM_OFF;

    const int tid = threadIdx.x;
    const int bid = blockIdx.x;
    const int j0  = (bid >> 1) * 8;
    const int m0  = (bid & 1) * 64;
    const int gwarp = bid * NWARP + (tid >> 5);   // 0..1535
    const int lane  = tid & 31;

    int barid = 0;
    if (bid == 0 && tid == 0) atomicExch(&g_bar[NBAR - 1], 0u);

    float c_reg[4];

    // ===== encoder =====
    load_weights(Ws, bsum, Wih_e, Whh_e, bih_e, bhh_e, j0, tid);
    for (int idx = bid * NTHR + tid; idx < B_ * H_; idx += NBLK * NTHR)
        g_h[0][idx] = 0.0f;
#pragma unroll
    for (int i = 0; i < 4; ++i) c_reg[i] = 0.0f;
    grid_bar(barid++, tid, bid);

    for (int t = 0; t < T_; ++t) {
        gemm_cell_step(seq + t * I_, T_ * I_,
                       g_h[t & 1], g_h[(t + 1) & 1],
                       Ws, As, Xs, bsum, c_reg, m0, j0, tid);
        grid_bar(barid++, tid, bid);
    }
    // h_n in g_h[0]

    // ===== VAE =====
    {
        const float* hn = g_h[0];
        for (int idx = gwarp; idx < B_ * L_; idx += NBLK * NWARP) {
            int b = idx >> 6, l = idx & 63;
            const float* hb = hn + b * H_;
            const float* wm = Wm + l * H_;
            const float* wv = Wv + l * H_;
            float sm = 0.0f, sv = 0.0f;
#pragma unroll 4
            for (int k = lane; k < H_; k += 32) {
                float hv = hb[k];
                sm += hv * wm[k];
                sv += hv * wv[k];
            }
#pragma unroll
            for (int off = 16; off > 0; off >>= 1) {
                sm += __shfl_down_sync(0xffffffffu, sm, off);
                sv += __shfl_down_sync(0xffffffffu, sv, off);
            }
            if (lane == 0) {
                sm += bm[l];
                sv += bv[l];
                out_mean[b * L_ + l] = sm;
                out_lv  [b * L_ + l] = sv;
                g_z[b * L_ + l] = sm + eps[b * L_ + l] * expf(0.5f * sv);
            }
        }
    }
    grid_bar(barid++, tid, bid);

    // ===== decoder init =====
    load_weights(Ws, bsum, Wih_d, Whh_d, bih_d, bhh_d, j0, tid);
    {
        int gt = bid * NTHR + tid;               // 0..49151
        for (int idx = gt; idx < B_ * H_; idx += NBLK * NTHR) {
            int b = idx >> 9, j = idx & 511;
            const float* zb = g_z + b * L_;
            const float* wr = Wi + j * L_;
            float s = bi[j];
#pragma unroll 16
            for (int k = 0; k < L_; ++k) s += zb[k] * wr[k];
            g_h[0][b * H_ + j] = s;
        }
        if (gt < B_ * L_) g_x[gt] = 0.0f;
#pragma unroll
        for (int i = 0; i < 4; ++i) c_reg[i] = 0.0f;
    }
    grid_bar(barid++, tid, bid);

    // ===== decoder loop =====
    for (int s = 0; s < DEC_; ++s) {
        gemm_cell_step(g_x, L_,
                       g_h[s & 1], g_h[(s + 1) & 1],
                       Ws, As, Xs, bsum, c_reg, m0, j0, tid);
        grid_bar(barid++, tid, bid);

        const float* hcur = g_h[(s + 1) & 1];
        for (int idx = gwarp; idx < B_ * I_; idx += NBLK * NWARP) {
            int b = idx >> 6, i = idx & 63;
            const float* hb = hcur + b * H_;
            const float* wr = Wo + i * H_;
            float sum = 0.0f;
#pragma unroll 4
            for (int k = lane; k < H_; k += 32) sum += hb[k] * wr[k];
#pragma unroll
            for (int off = 16; off > 0; off >>= 1)
                sum += __shfl_down_sync(0xffffffffu, sum, off);
            if (lane == 0) {
                float v = sum + bo[i];
                g_x[b * I_ + i] = v;
                out_xhat[(b * DEC_ + s) * I_ + i] = v;
            }
        }
        grid_bar(barid++, tid, bid);
    }
}

// ---------------- launch ----------------
extern "C" void kernel_launch(void* const* d_in, const int* in_sizes, int n_in,
                              void* d_out, int out_size)
{
    (void)in_sizes; (void)n_in; (void)out_size;

    const float* seq    = (const float*)d_in[0];
    const float* eps    = (const float*)d_in[2];
    const float* Wih_e  = (const float*)d_in[3];
    const float* Whh_e  = (const float*)d_in[4];
    const float* bih_e  = (const float*)d_in[5];
    const float* bhh_e  = (const float*)d_in[6];
    const float* Wm     = (const float*)d_in[7];
    const float* bm     = (const float*)d_in[8];
    const float* Wv     = (const float*)d_in[9];
    const float* bv     = (const float*)d_in[10];
    const float* Wi     = (const float*)d_in[11];
    const float* bi     = (const float*)d_in[12];
    const float* Wih_d  = (const float*)d_in[13];
    const float* Whh_d  = (const float*)d_in[14];
    const float* bih_d  = (const float*)d_in[15];
    const float* bhh_d  = (const float*)d_in[16];
    const float* Wo     = (const float*)d_in[17];
    const float* bo     = (const float*)d_in[18];

    float* out      = (float*)d_out;
    float* out_xhat = out;
    float* out_mean = out + B_ * DEC_ * I_;
    float* out_lv   = out_mean + B_ * L_;

    cudaFuncSetAttribute(vae_mega, cudaFuncAttributeMaxDynamicSharedMemorySize,
                         SMEM_BYTES);

    vae_mega<<<NBLK, NTHR, SMEM_BYTES>>>(
        seq, eps,
        Wih_e, Whh_e, bih_e, bhh_e,
        Wm, bm, Wv, bv, Wi, bi,
        Wih_d, Whh_d, bih_d, bhh_d,
        Wo, bo,
        out_xhat, out_mean, out_lv);
}

// round 13
// speedup vs baseline: 1.0931x; 1.0463x over previous
#include <cuda_runtime.h>
#include <math.h>

#define B_   128
#define T_   512
#define I_   64
#define H_   512
#define L_   64
#define DEC_ 100

typedef unsigned long long ull;

#define NBLK   128
#define NTHR   384
#define NWARP  12
#define NBAR   715           // 1 + 512 + 1 + 1 + 200

// ---------------- device globals ----------------
__device__ unsigned g_bar[1024];
// blocked-rotated h tiles: [buf][half][chunk 0..7][64 m][64 k] (16KB per chunk tile)
__device__ __align__(16) float g_hT[2 * 2 * 8 * 4096];
// blocked-rotated seq tiles: [half][t][64 m][64 k]
__device__ __align__(16) float g_seqblk[2 * 512 * 4096];
// blocked-rotated decoder x: [half][64 m][64 k]
__device__ __align__(16) float g_xblk[2 * 4096];
__device__ __align__(16) float g_hflat[B_ * H_];
__device__ __align__(16) float g_z[B_ * L_];

__device__ __forceinline__ float sigf(float v) { return 1.0f / (1.0f + expf(-v)); }

__device__ __forceinline__ void ffma2(ull& d, ull a, ull b) {
    asm("fma.rn.f32x2 %0, %1, %2, %0;" : "+l"(d) : "l"(a), "l"(b));
}

__device__ __forceinline__ unsigned smem_u32(const void* p) {
    return (unsigned)__cvta_generic_to_shared(p);
}

// ---------------- mbarrier + bulk-copy helpers ----------------
__device__ __forceinline__ void mbar_init(unsigned a, unsigned cnt) {
    asm volatile("mbarrier.init.shared.b64 [%0], %1;" :: "r"(a), "r"(cnt) : "memory");
}
// one-shot producer: re-arm expect_tx then launch 16KB bulk copy
__device__ __forceinline__ void bulk_ld16k(unsigned dst, const float* src, unsigned mbar) {
    asm volatile("mbarrier.arrive.expect_tx.shared.b64 _, [%0], %1;"
                 :: "r"(mbar), "r"(16384u) : "memory");
    asm volatile("cp.async.bulk.shared::cluster.global.mbarrier::complete_tx::bytes "
                 "[%0], [%1], %2, [%3];"
                 :: "r"(dst), "l"(src), "r"(16384u), "r"(mbar) : "memory");
}
__device__ __forceinline__ void mbar_wait(unsigned mbar, unsigned ph) {
    unsigned done;
    asm volatile("{\n\t.reg .pred p;\n\t"
                 "mbarrier.try_wait.parity.acquire.cta.shared::cta.b64 p, [%1], %2;\n\t"
                 "selp.b32 %0, 1, 0, p;\n\t}"
                 : "=r"(done) : "r"(mbar), "r"(ph) : "memory");
    if (!done) {
        asm volatile("{\n\t.reg .pred P1;\n"
                     "WL_%=:\n\t"
                     "mbarrier.try_wait.parity.acquire.cta.shared::cta.b64 P1, [%0], %1, 0x989680;\n\t"
                     "@P1 bra.uni WD_%=;\n\t"
                     "bra.uni WL_%=;\n"
                     "WD_%=:\n\t}" :: "r"(mbar), "r"(ph) : "memory");
    }
}

// ---------------- software grid barrier (128 co-resident blocks) ----------------
__device__ __forceinline__ void grid_bar(int idx, int tid, int bid)
{
    __threadfence();
    __syncthreads();
    if (tid == 0) {
        atomicAdd(&g_bar[idx], 1u);
        volatile unsigned* p = &g_bar[idx];
        while (*p < (unsigned)NBLK) {}
        __threadfence();
        if (bid == 0 && idx > 0) atomicExch(&g_bar[idx - 1], 0u);
    }
    __syncthreads();
}

// group-local barrier (4 warps = 128 threads); named barrier ids 1..3
__device__ __forceinline__ void bar_group(int g)
{
    asm volatile("bar.sync %0, %1;" :: "r"(g + 1), "r"(128) : "memory");
}

// ---------------- smem layout ----------------
#define WS_STR   580
#define WS_OFF   0
#define AS_OFF   (32 * WS_STR)                  // 18560 (3 groups x 2 bufs x 4096)
#define XS_OFF   (AS_OFF + 3 * 2 * 4096)        // 43136 (2 x 64 x 33)
#define BSUM_OFF (XS_OFF + 2 * 64 * 33)         // 47360
#define SMEM_FLTS (BSUM_OFF + 32)               // 47392
#define MBAR_BYTE (SMEM_FLTS * 4)               // 189568 (6 mbars x 8B)
#define SMEM_BYTES (MBAR_BYTE + 64)             // 189632

// rotation used everywhere: stored col = (jc + 8*((m>>2)&7)) & 63  (jc 4-group aligned safe)
__device__ __forceinline__ int rotc(int m, int jc) {
    return (jc + 8 * ((m >> 2) & 7)) & 63;
}

// ---------------- resident weight loader (natural [n][k] layout) ----------------
__device__ __forceinline__ void load_weights(float* Ws, float* bsum,
    const float* __restrict__ Wih, const float* __restrict__ Whh,
    const float* __restrict__ bih, const float* __restrict__ bhh,
    int j0, int tid)
{
    __syncthreads();
    for (int q = tid; q < 32 * 16; q += NTHR) {
        int r = q >> 4, k4 = q & 15;
        int row = (r >> 3) * H_ + j0 + (r & 7);
        *(float4*)(Ws + r * WS_STR + k4 * 4) = *(const float4*)(Wih + row * I_ + k4 * 4);
    }
    for (int q = tid; q < 32 * 128; q += NTHR) {
        int r = q >> 7, k4 = q & 127;
        int row = (r >> 3) * H_ + j0 + (r & 7);
        *(float4*)(Ws + r * WS_STR + 64 + k4 * 4) = *(const float4*)(Whh + row * H_ + k4 * 4);
    }
    if (tid < 32) {
        int g = tid >> 3, jj = tid & 7;
        bsum[tid] = bih[g * H_ + j0 + jj] + bhh[g * H_ + j0 + jj];
    }
    __syncthreads();
}

// ---------------- fused GEMM + cell update, 3-way split-K, bulk-copy staged ----------------
__device__ __forceinline__ void gemm_cell_step(
    const float* __restrict__ xtile,       // 4096-float blocked tile (chunk 0)
    const float* __restrict__ hTr,         // 8 x 4096 blocked h tiles (read)
    float* __restrict__ hTw,               // blocked h tiles (write)
    float* __restrict__ hflat,
    const float* Ws, float* As, float* Xs, const float* bsum,
    unsigned mb_blk, int& ring,
    float* c_reg, int m0, int j0, int tid)
{
    const int g    = tid >> 7;
    const int gtid = tid & 127;
    const int tx   = gtid & 7;
    const int ty   = gtid >> 3;
    float* Asg = As + g * 8192;
    const int cbeg = 3 * g;
    const unsigned mbg = mb_blk + g * 16;     // this group's 2 mbars

    ull acc[4][4];
#pragma unroll
    for (int i = 0; i < 4; ++i)
#pragma unroll
        for (int j = 0; j < 4; ++j) acc[i][j] = 0ull;

    const int colbase = 8 * (ty & 7);
    const float* b0p = Ws + (tx +  0) * WS_STR;
    const float* b1p = Ws + (tx +  8) * WS_STR;
    const float* b2p = Ws + (tx + 16) * WS_STR;
    const float* b3p = Ws + (tx + 24) * WS_STR;

    const float* srcs[3];
    srcs[0] = (cbeg == 0) ? xtile : hTr + (cbeg - 1) * 4096;
    srcs[1] = hTr + (cbeg + 0) * 4096;
    srcs[2] = hTr + (cbeg + 1) * 4096;

    // both buffers are provably free at step start (prev step's bar_groups + grid_bar)
    if (gtid == 0) {
        asm volatile("fence.proxy.async;" ::: "memory");
        bulk_ld16k(smem_u32(Asg + (ring & 1) * 4096),       srcs[0], mbg + (ring & 1) * 8);
        bulk_ld16k(smem_u32(Asg + ((ring + 1) & 1) * 4096), srcs[1], mbg + ((ring + 1) & 1) * 8);
    }

#pragma unroll
    for (int ci = 0; ci < 3; ++ci) {
        const int rr = ring + ci;
        mbar_wait(mbg + (rr & 1) * 8, (rr >> 1) & 1);
        const float* Af = Asg + (rr & 1) * 4096;
        const int kb = (cbeg + ci) * 64;
        const float* a0p = Af + (4 * ty + 0) * 64;
        const float* a1p = Af + (4 * ty + 1) * 64;
        const float* a2p = Af + (4 * ty + 2) * 64;
        const float* a3p = Af + (4 * ty + 3) * 64;
#pragma unroll 4
        for (int kq = 0; kq < 16; ++kq) {      // 4 k per iter, LDS.128
            int col = (4 * kq + colbase) & 63;
            ulonglong2 A0 = *(const ulonglong2*)(a0p + col);
            ulonglong2 A1 = *(const ulonglong2*)(a1p + col);
            ulonglong2 A2 = *(const ulonglong2*)(a2p + col);
            ulonglong2 A3 = *(const ulonglong2*)(a3p + col);
            ulonglong2 B0 = *(const ulonglong2*)(b0p + kb + 4 * kq);
            ulonglong2 B1 = *(const ulonglong2*)(b1p + kb + 4 * kq);
            ulonglong2 B2 = *(const ulonglong2*)(b2p + kb + 4 * kq);
            ulonglong2 B3 = *(const ulonglong2*)(b3p + kb + 4 * kq);
            ffma2(acc[0][0], A0.x, B0.x); ffma2(acc[0][1], A0.x, B1.x);
            ffma2(acc[0][2], A0.x, B2.x); ffma2(acc[0][3], A0.x, B3.x);
            ffma2(acc[1][0], A1.x, B0.x); ffma2(acc[1][1], A1.x, B1.x);
            ffma2(acc[1][2], A1.x, B2.x); ffma2(acc[1][3], A1.x, B3.x);
            ffma2(acc[2][0], A2.x, B0.x); ffma2(acc[2][1], A2.x, B1.x);
            ffma2(acc[2][2], A2.x, B2.x); ffma2(acc[2][3], A2.x, B3.x);
            ffma2(acc[3][0], A3.x, B0.x); ffma2(acc[3][1], A3.x, B1.x);
            ffma2(acc[3][2], A3.x, B2.x); ffma2(acc[3][3], A3.x, B3.x);
            ffma2(acc[0][0], A0.y, B0.y); ffma2(acc[0][1], A0.y, B1.y);
            ffma2(acc[0][2], A0.y, B2.y); ffma2(acc[0][3], A0.y, B3.y);
            ffma2(acc[1][0], A1.y, B0.y); ffma2(acc[1][1], A1.y, B1.y);
            ffma2(acc[1][2], A1.y, B2.y); ffma2(acc[1][3], A1.y, B3.y);
            ffma2(acc[2][0], A2.y, B0.y); ffma2(acc[2][1], A2.y, B1.y);
            ffma2(acc[2][2], A2.y, B2.y); ffma2(acc[2][3], A2.y, B3.y);
            ffma2(acc[3][0], A3.y, B0.y); ffma2(acc[3][1], A3.y, B1.y);
            ffma2(acc[3][2], A3.y, B2.y); ffma2(acc[3][3], A3.y, B3.y);
        }
        if (ci == 0) {
            bar_group(g);                      // buf(ring) drained by whole group
            if (gtid == 0)
                bulk_ld16k(smem_u32(Asg + ((ring + 2) & 1) * 4096), srcs[2],
                           mbg + ((ring + 2) & 1) * 8);
        } else if (ci == 1) {
            bar_group(g);
        }
    }
    ring += 3;

    // epilogue: lo+hi horizontal reduce
    float s[4][4];
#pragma unroll
    for (int i = 0; i < 4; ++i)
#pragma unroll
        for (int j = 0; j < 4; ++j) {
            ull v = acc[i][j];
            s[i][j] = __uint_as_float((unsigned)(v & 0xffffffffull))
                    + __uint_as_float((unsigned)(v >> 32));
        }

    if (g > 0) {   // groups 1,2 publish partials
        float* Xg = Xs + (g - 1) * (64 * 33);
#pragma unroll
        for (int i = 0; i < 4; ++i)
#pragma unroll
            for (int j = 0; j < 4; ++j)
                Xg[(4 * ty + i) * 33 + tx + 8 * j] = s[i][j];
    }
    __syncthreads();
    if (g == 0) {  // combine + cell update
        const int cH = j0 >> 6;                // h chunk this block's j-slice lands in
        const int jc = (j0 & 63) + tx;         // col within that chunk
#pragma unroll
        for (int i = 0; i < 4; ++i) {
            int m = 4 * ty + i;
            float gi = s[i][0] + Xs[m * 33 + tx]      + Xs[64*33 + m * 33 + tx]      + bsum[tx];
            float gf = s[i][1] + Xs[m * 33 + tx + 8]  + Xs[64*33 + m * 33 + tx + 8]  + bsum[8 + tx];
            float gg = s[i][2] + Xs[m * 33 + tx + 16] + Xs[64*33 + m * 33 + tx + 16] + bsum[16 + tx];
            float go = s[i][3] + Xs[m * 33 + tx + 24] + Xs[64*33 + m * 33 + tx + 24] + bsum[24 + tx];
            float cn = sigf(gf) * c_reg[i] + sigf(gi) * tanhf(gg);
            float hn = sigf(go) * tanhf(cn);
            c_reg[i] = cn;
            hflat[(m0 + m) * H_ + j0 + tx] = hn;
            hTw[(cH * 64 + m) * 64 + rotc(m, jc)] = hn;
        }
    }
    __syncthreads();
}

// ---------------- the megakernel ----------------
__global__ void __launch_bounds__(NTHR, 1)
vae_mega(const float* __restrict__ seq,  const float* __restrict__ eps,
         const float* __restrict__ Wih_e, const float* __restrict__ Whh_e,
         const float* __restrict__ bih_e, const float* __restrict__ bhh_e,
         const float* __restrict__ Wm, const float* __restrict__ bm,
         const float* __restrict__ Wv, const float* __restrict__ bv,
         const float* __restrict__ Wi, const float* __restrict__ bi,
         const float* __restrict__ Wih_d, const float* __restrict__ Whh_d,
         const float* __restrict__ bih_d, const float* __restrict__ bhh_d,
         const float* __restrict__ Wo, const float* __restrict__ bo,
         float* __restrict__ out_xhat, float* __restrict__ out_mean,
         float* __restrict__ out_lv)
{
    extern __shared__ float smem[];
    float* Ws   = smem + WS_OFF;
    float* As   = smem + AS_OFF;
    float* Xs   = smem + XS_OFF;
    float* bsum = smem + BSUM_OFF;

    const int tid = threadIdx.x;
    const int bid = blockIdx.x;
    const int j0  = (bid >> 1) * 8;
    const int m0  = (bid & 1) * 64;
    const int half = m0 >> 6;
    const int gwarp = bid * NWARP + (tid >> 5);
    const int lane  = tid & 31;
    const unsigned mb_blk = smem_u32(smem) + MBAR_BYTE;

    if (tid == 0) {
#pragma unroll
        for (int i = 0; i < 6; ++i) mbar_init(mb_blk + i * 8, 1);
    }
    int barid = 0;
    if (bid == 0 && tid == 0) atomicExch(&g_bar[NBAR - 1], 0u);

    float c_reg[4];
    int ring = 0;

    // ===== pre-phase: weights, zero h tiles, tile seq into blocked layout =====
    load_weights(Ws, bsum, Wih_e, Whh_e, bih_e, bhh_e, j0, tid);
    {
        int gt = bid * NTHR + tid;                  // 0..49151
        for (int idx = gt; idx < 2 * 8 * 4096; idx += NBLK * NTHR)
            g_hT[idx] = 0.0f;                       // buf0, both halves
        // re-tile seq: 2^20 float4 items
        for (int it = gt; it < (1 << 20); it += NBLK * NTHR) {
            int i4 = it & 15;
            int m  = (it >> 4) & 63;
            int t  = (it >> 10) & 511;
            int hf = it >> 19;
            float4 v = *(const float4*)(seq + (((hf * 64 + m) * 512 + t) * 64 + i4 * 4));
            *(float4*)(g_seqblk + (hf * 512 + t) * 4096 + m * 64 + rotc(m, i4 * 4)) = v;
        }
#pragma unroll
        for (int i = 0; i < 4; ++i) c_reg[i] = 0.0f;
    }
    grid_bar(barid++, tid, bid);

    // ===== encoder =====
    for (int t = 0; t < T_; ++t) {
        const float* xt  = g_seqblk + (half * 512 + t) * 4096;
        const float* hTr = g_hT + ((t & 1) * 2 + half) * 32768;
        float*       hTw = g_hT + ((((t + 1) & 1) * 2) + half) * 32768;
        gemm_cell_step(xt, hTr, hTw, g_hflat,
                       Ws, As, Xs, bsum, mb_blk, ring, c_reg, m0, j0, tid);
        grid_bar(barid++, tid, bid);
    }
    // h_n flat in g_hflat; blocked in buf 0

    // ===== VAE =====
    {
        const float* hn = g_hflat;
        for (int idx = gwarp; idx < B_ * L_; idx += NBLK * NWARP) {
            int b = idx >> 6, l = idx & 63;
            const float* hb = hn + b * H_;
            const float* wm = Wm + l * H_;
            const float* wv = Wv + l * H_;
            float sm = 0.0f, sv = 0.0f;
#pragma unroll 4
            for (int k = lane; k < H_; k += 32) {
                float hv = hb[k];
                sm += hv * wm[k];
                sv += hv * wv[k];
            }
#pragma unroll
            for (int off = 16; off > 0; off >>= 1) {
                sm += __shfl_down_sync(0xffffffffu, sm, off);
                sv += __shfl_down_sync(0xffffffffu, sv, off);
            }
            if (lane == 0) {
                sm += bm[l];
                sv += bv[l];
                out_mean[b * L_ + l] = sm;
                out_lv  [b * L_ + l] = sv;
                g_z[b * L_ + l] = sm + eps[b * L_ + l] * expf(0.5f * sv);
            }
        }
    }
    grid_bar(barid++, tid, bid);

    // ===== decoder init =====
    load_weights(Ws, bsum, Wih_d, Whh_d, bih_d, bhh_d, j0, tid);
    {
        int gt = bid * NTHR + tid;
        for (int idx = gt; idx < B_ * H_; idx += NBLK * NTHR) {
            int b = idx >> 9, j = idx & 511;
            const float* zb = g_z + b * L_;
            const float* wr = Wi + j * L_;
            float s = bi[j];
#pragma unroll 16
            for (int k = 0; k < L_; ++k) s += zb[k] * wr[k];
            // write blocked h0 into buf 0
            int hf = b >> 6, m = b & 63, cH = j >> 6, jc = j & 63;
            g_hT[hf * 32768 + (cH * 64 + m) * 64 + rotc(m, jc)] = s;
        }
        for (int idx = gt; idx < 2 * 4096; idx += NBLK * NTHR)
            g_xblk[idx] = 0.0f;
#pragma unroll
        for (int i = 0; i < 4; ++i) c_reg[i] = 0.0f;
    }
    grid_bar(barid++, tid, bid);

    // ===== decoder loop =====
    for (int s = 0; s < DEC_; ++s) {
        const float* xt  = g_xblk + half * 4096;
        const float* hTr = g_hT + ((s & 1) * 2 + half) * 32768;
        float*       hTw = g_hT + ((((s + 1) & 1) * 2) + half) * 32768;
        gemm_cell_step(xt, hTr, hTw, g_hflat,
                       Ws, As, Xs, bsum, mb_blk, ring, c_reg, m0, j0, tid);
        grid_bar(barid++, tid, bid);

        for (int idx = gwarp; idx < B_ * I_; idx += NBLK * NWARP) {
            int b = idx >> 6, i = idx & 63;
            const float* hb = g_hflat + b * H_;
            const float* wr = Wo + i * H_;
            float sum = 0.0f;
#pragma unroll 4
            for (int k = lane; k < H_; k += 32) sum += hb[k] * wr[k];
#pragma unroll
            for (int off = 16; off > 0; off >>= 1)
                sum += __shfl_down_sync(0xffffffffu, sum, off);
            if (lane == 0) {
                float v = sum + bo[i];
                int hf = b >> 6, m = b & 63;
                g_xblk[hf * 4096 + m * 64 + rotc(m, i)] = v;
                out_xhat[(b * DEC_ + s) * I_ + i] = v;
            }
        }
        grid_bar(barid++, tid, bid);
    }
}

// ---------------- launch ----------------
extern "C" void kernel_launch(void* const* d_in, const int* in_sizes, int n_in,
                              void* d_out, int out_size)
{
    (void)in_sizes; (void)n_in; (void)out_size;

    const float* seq    = (const float*)d_in[0];
    const float* eps    = (const float*)d_in[2];
    const float* Wih_e  = (const float*)d_in[3];
    const float* Whh_e  = (const float*)d_in[4];
    const float* bih_e  = (const float*)d_in[5];
    const float* bhh_e  = (const float*)d_in[6];
    const float* Wm     = (const float*)d_in[7];
    const float* bm     = (const float*)d_in[8];
    const float* Wv     = (const float*)d_in[9];
    const float* bv     = (const float*)d_in[10];
    const float* Wi     = (const float*)d_in[11];
    const float* bi     = (const float*)d_in[12];
    const float* Wih_d  = (const float*)d_in[13];
    const float* Whh_d  = (const float*)d_in[14];
    const float* bih_d  = (const float*)d_in[15];
    const float* bhh_d  = (const float*)d_in[16];
    const float* Wo     = (const float*)d_in[17];
    const float* bo     = (const float*)d_in[18];

    float* out      = (float*)d_out;
    float* out_xhat = out;
    float* out_mean = out + B_ * DEC_ * I_;
    float* out_lv   = out_mean + B_ * L_;

    cudaFuncSetAttribute(vae_mega, cudaFuncAttributeMaxDynamicSharedMemorySize,
                         SMEM_BYTES);

    vae_mega<<<NBLK, NTHR, SMEM_BYTES>>>(
        seq, eps,
        Wih_e, Whh_e, bih_e, bhh_e,
        Wm, bm, Wv, bv, Wi, bi,
        Wih_d, Whh_d, bih_d, bhh_d,
        Wo, bo,
        out_xhat, out_mean, out_lv);
}

// round 14
// speedup vs baseline: 1.1033x; 1.0093x over previous
#include <cuda_runtime.h>
#include <math.h>

#define B_   128
#define T_   512
#define I_   64
#define H_   512
#define L_   64
#define DEC_ 100

typedef unsigned long long ull;

#define NBLK   128
#define NTHR   384
#define NWARP  12
#define NBAR   715           // 1 + 512 + 1 + 1 + 200

// ---------------- device globals ----------------
__device__ unsigned g_bar[1024];
// blocked-rotated h tiles: [buf][half][chunk 0..7][64 m][64 k] (16KB per chunk tile)
__device__ __align__(16) float g_hT[2 * 2 * 8 * 4096];
// blocked-rotated seq tiles: [half][t][64 m][64 k]
__device__ __align__(16) float g_seqblk[2 * 512 * 4096];
// blocked-rotated decoder x: [half][64 m][64 k]
__device__ __align__(16) float g_xblk[2 * 4096];
__device__ __align__(16) float g_hflat[B_ * H_];
__device__ __align__(16) float g_z[B_ * L_];

__device__ __forceinline__ float sigf(float v) { return 1.0f / (1.0f + expf(-v)); }

__device__ __forceinline__ void ffma2(ull& d, ull a, ull b) {
    asm("fma.rn.f32x2 %0, %1, %2, %0;" : "+l"(d) : "l"(a), "l"(b));
}

__device__ __forceinline__ unsigned smem_u32(const void* p) {
    return (unsigned)__cvta_generic_to_shared(p);
}

// ---------------- mbarrier + bulk-copy helpers ----------------
__device__ __forceinline__ void mbar_init(unsigned a, unsigned cnt) {
    asm volatile("mbarrier.init.shared.b64 [%0], %1;" :: "r"(a), "r"(cnt) : "memory");
}
// one-shot producer: re-arm expect_tx then launch 16KB bulk copy
__device__ __forceinline__ void bulk_ld16k(unsigned dst, const float* src, unsigned mbar) {
    asm volatile("mbarrier.arrive.expect_tx.shared.b64 _, [%0], %1;"
                 :: "r"(mbar), "r"(16384u) : "memory");
    asm volatile("cp.async.bulk.shared::cluster.global.mbarrier::complete_tx::bytes "
                 "[%0], [%1], %2, [%3];"
                 :: "r"(dst), "l"(src), "r"(16384u), "r"(mbar) : "memory");
}
__device__ __forceinline__ void mbar_wait(unsigned mbar, unsigned ph) {
    unsigned done;
    asm volatile("{\n\t.reg .pred p;\n\t"
                 "mbarrier.try_wait.parity.acquire.cta.shared::cta.b64 p, [%1], %2;\n\t"
                 "selp.b32 %0, 1, 0, p;\n\t}"
                 : "=r"(done) : "r"(mbar), "r"(ph) : "memory");
    if (!done) {
        asm volatile("{\n\t.reg .pred P1;\n"
                     "WL_%=:\n\t"
                     "mbarrier.try_wait.parity.acquire.cta.shared::cta.b64 P1, [%0], %1, 0x989680;\n\t"
                     "@P1 bra.uni WD_%=;\n\t"
                     "bra.uni WL_%=;\n"
                     "WD_%=:\n\t}" :: "r"(mbar), "r"(ph) : "memory");
    }
}

// ---------------- software grid barrier (128 co-resident blocks) ----------------
__device__ __forceinline__ void grid_bar(int idx, int tid, int bid)
{
    __threadfence();
    __syncthreads();
    if (tid == 0) {
        atomicAdd(&g_bar[idx], 1u);
        volatile unsigned* p = &g_bar[idx];
        while (*p < (unsigned)NBLK) {}
        __threadfence();
        if (bid == 0 && idx > 0) atomicExch(&g_bar[idx - 1], 0u);
    }
    __syncthreads();
}

// group-local barrier (4 warps = 128 threads); named barrier ids 1..3
__device__ __forceinline__ void bar_group(int g)
{
    asm volatile("bar.sync %0, %1;" :: "r"(g + 1), "r"(128) : "memory");
}

// ---------------- smem layout ----------------
#define WS_STR   580
#define WS_OFF   0
#define AS_OFF   (32 * WS_STR)                  // 18560 (3 groups x 2 bufs x 4096)
#define XS_OFF   (AS_OFF + 3 * 2 * 4096)        // 43136 (2 x 64 x 33)
#define BSUM_OFF (XS_OFF + 2 * 64 * 33)         // 47360
#define SMEM_FLTS (BSUM_OFF + 32)               // 47392
#define MBAR_BYTE (SMEM_FLTS * 4)               // 189568 (6 mbars x 8B)
#define SMEM_BYTES (MBAR_BYTE + 64)             // 189632

// rotation used everywhere: stored col = (jc + 8*((m>>2)&7)) & 63  (jc 4-group aligned safe)
__device__ __forceinline__ int rotc(int m, int jc) {
    return (jc + 8 * ((m >> 2) & 7)) & 63;
}

// ---------------- resident weight loader (natural [n][k] layout) ----------------
__device__ __forceinline__ void load_weights(float* Ws, float* bsum,
    const float* __restrict__ Wih, const float* __restrict__ Whh,
    const float* __restrict__ bih, const float* __restrict__ bhh,
    int j0, int tid)
{
    __syncthreads();
    for (int q = tid; q < 32 * 16; q += NTHR) {
        int r = q >> 4, k4 = q & 15;
        int row = (r >> 3) * H_ + j0 + (r & 7);
        *(float4*)(Ws + r * WS_STR + k4 * 4) = *(const float4*)(Wih + row * I_ + k4 * 4);
    }
    for (int q = tid; q < 32 * 128; q += NTHR) {
        int r = q >> 7, k4 = q & 127;
        int row = (r >> 3) * H_ + j0 + (r & 7);
        *(float4*)(Ws + r * WS_STR + 64 + k4 * 4) = *(const float4*)(Whh + row * H_ + k4 * 4);
    }
    if (tid < 32) {
        int g = tid >> 3, jj = tid & 7;
        bsum[tid] = bih[g * H_ + j0 + jj] + bhh[g * H_ + j0 + jj];
    }
    __syncthreads();
}

// ---------------- fused GEMM + cell update, 3-way split-K, bulk-copy staged ----------------
__device__ __forceinline__ void gemm_cell_step(
    const float* __restrict__ xtile,       // 4096-float blocked tile (chunk 0)
    const float* __restrict__ hTr,         // 8 x 4096 blocked h tiles (read)
    float* __restrict__ hTw,               // blocked h tiles (write)
    float* __restrict__ hflat,
    const float* Ws, float* As, float* Xs, const float* bsum,
    unsigned mb_blk, int& ring,
    float* c_reg, int m0, int j0, int tid)
{
    const int g    = tid >> 7;
    const int gtid = tid & 127;
    const int tx   = gtid & 7;
    const int ty   = gtid >> 3;
    float* Asg = As + g * 8192;
    const int cbeg = 3 * g;
    const unsigned mbg = mb_blk + g * 16;     // this group's 2 mbars

    ull acc[4][4];
#pragma unroll
    for (int i = 0; i < 4; ++i)
#pragma unroll
        for (int j = 0; j < 4; ++j) acc[i][j] = 0ull;

    const int colbase = 8 * (ty & 7);
    const float* b0p = Ws + (tx +  0) * WS_STR;
    const float* b1p = Ws + (tx +  8) * WS_STR;
    const float* b2p = Ws + (tx + 16) * WS_STR;
    const float* b3p = Ws + (tx + 24) * WS_STR;

    const float* srcs[3];
    srcs[0] = (cbeg == 0) ? xtile : hTr + (cbeg - 1) * 4096;
    srcs[1] = hTr + (cbeg + 0) * 4096;
    srcs[2] = hTr + (cbeg + 1) * 4096;

    // both buffers are provably free at step start (prev step's bar_groups + grid_bar)
    if (gtid == 0) {
        asm volatile("fence.proxy.async;" ::: "memory");
        bulk_ld16k(smem_u32(Asg + (ring & 1) * 4096),       srcs[0], mbg + (ring & 1) * 8);
        bulk_ld16k(smem_u32(Asg + ((ring + 1) & 1) * 4096), srcs[1], mbg + ((ring + 1) & 1) * 8);
    }

#pragma unroll
    for (int ci = 0; ci < 3; ++ci) {
        const int rr = ring + ci;
        mbar_wait(mbg + (rr & 1) * 8, (rr >> 1) & 1);
        const float* Af = Asg + (rr & 1) * 4096;
        const int kb = (cbeg + ci) * 64;
        const float* a0p = Af + (4 * ty + 0) * 64;
        const float* a1p = Af + (4 * ty + 1) * 64;
        const float* a2p = Af + (4 * ty + 2) * 64;
        const float* a3p = Af + (4 * ty + 3) * 64;
#pragma unroll 4
        for (int kq = 0; kq < 16; ++kq) {      // 4 k per iter, LDS.128
            int col = (4 * kq + colbase) & 63;
            ulonglong2 A0 = *(const ulonglong2*)(a0p + col);
            ulonglong2 A1 = *(const ulonglong2*)(a1p + col);
            ulonglong2 A2 = *(const ulonglong2*)(a2p + col);
            ulonglong2 A3 = *(const ulonglong2*)(a3p + col);
            ulonglong2 B0 = *(const ulonglong2*)(b0p + kb + 4 * kq);
            ulonglong2 B1 = *(const ulonglong2*)(b1p + kb + 4 * kq);
            ulonglong2 B2 = *(const ulonglong2*)(b2p + kb + 4 * kq);
            ulonglong2 B3 = *(const ulonglong2*)(b3p + kb + 4 * kq);
            ffma2(acc[0][0], A0.x, B0.x); ffma2(acc[0][1], A0.x, B1.x);
            ffma2(acc[0][2], A0.x, B2.x); ffma2(acc[0][3], A0.x, B3.x);
            ffma2(acc[1][0], A1.x, B0.x); ffma2(acc[1][1], A1.x, B1.x);
            ffma2(acc[1][2], A1.x, B2.x); ffma2(acc[1][3], A1.x, B3.x);
            ffma2(acc[2][0], A2.x, B0.x); ffma2(acc[2][1], A2.x, B1.x);
            ffma2(acc[2][2], A2.x, B2.x); ffma2(acc[2][3], A2.x, B3.x);
            ffma2(acc[3][0], A3.x, B0.x); ffma2(acc[3][1], A3.x, B1.x);
            ffma2(acc[3][2], A3.x, B2.x); ffma2(acc[3][3], A3.x, B3.x);
            ffma2(acc[0][0], A0.y, B0.y); ffma2(acc[0][1], A0.y, B1.y);
            ffma2(acc[0][2], A0.y, B2.y); ffma2(acc[0][3], A0.y, B3.y);
            ffma2(acc[1][0], A1.y, B0.y); ffma2(acc[1][1], A1.y, B1.y);
            ffma2(acc[1][2], A1.y, B2.y); ffma2(acc[1][3], A1.y, B3.y);
            ffma2(acc[2][0], A2.y, B0.y); ffma2(acc[2][1], A2.y, B1.y);
            ffma2(acc[2][2], A2.y, B2.y); ffma2(acc[2][3], A2.y, B3.y);
            ffma2(acc[3][0], A3.y, B0.y); ffma2(acc[3][1], A3.y, B1.y);
            ffma2(acc[3][2], A3.y, B2.y); ffma2(acc[3][3], A3.y, B3.y);
        }
        if (ci == 0) {
            bar_group(g);                      // buf(ring) drained by whole group
            if (gtid == 0)
                bulk_ld16k(smem_u32(Asg + ((ring + 2) & 1) * 4096), srcs[2],
                           mbg + ((ring + 2) & 1) * 8);
        } else if (ci == 1) {
            bar_group(g);
        }
    }
    ring += 3;

    // epilogue: lo+hi horizontal reduce
    float s[4][4];
#pragma unroll
    for (int i = 0; i < 4; ++i)
#pragma unroll
        for (int j = 0; j < 4; ++j) {
            ull v = acc[i][j];
            s[i][j] = __uint_as_float((unsigned)(v & 0xffffffffull))
                    + __uint_as_float((unsigned)(v >> 32));
        }

    if (g > 0) {   // groups 1,2 publish partials
        float* Xg = Xs + (g - 1) * (64 * 33);
#pragma unroll
        for (int i = 0; i < 4; ++i)
#pragma unroll
            for (int j = 0; j < 4; ++j)
                Xg[(4 * ty + i) * 33 + tx + 8 * j] = s[i][j];
    }
    __syncthreads();
    if (g == 0) {  // combine + cell update
        const int cH = j0 >> 6;                // h chunk this block's j-slice lands in
        const int jc = (j0 & 63) + tx;         // col within that chunk
#pragma unroll
        for (int i = 0; i < 4; ++i) {
            int m = 4 * ty + i;
            float gi = s[i][0] + Xs[m * 33 + tx]      + Xs[64*33 + m * 33 + tx]      + bsum[tx];
            float gf = s[i][1] + Xs[m * 33 + tx + 8]  + Xs[64*33 + m * 33 + tx + 8]  + bsum[8 + tx];
            float gg = s[i][2] + Xs[m * 33 + tx + 16] + Xs[64*33 + m * 33 + tx + 16] + bsum[16 + tx];
            float go = s[i][3] + Xs[m * 33 + tx + 24] + Xs[64*33 + m * 33 + tx + 24] + bsum[24 + tx];
            float cn = sigf(gf) * c_reg[i] + sigf(gi) * tanhf(gg);
            float hn = sigf(go) * tanhf(cn);
            c_reg[i] = cn;
            hflat[(m0 + m) * H_ + j0 + tx] = hn;
            hTw[(cH * 64 + m) * 64 + rotc(m, jc)] = hn;
        }
    }
    __syncthreads();
}

// ---------------- the megakernel ----------------
__global__ void __launch_bounds__(NTHR, 1)
vae_mega(const float* __restrict__ seq,  const float* __restrict__ eps,
         const float* __restrict__ Wih_e, const float* __restrict__ Whh_e,
         const float* __restrict__ bih_e, const float* __restrict__ bhh_e,
         const float* __restrict__ Wm, const float* __restrict__ bm,
         const float* __restrict__ Wv, const float* __restrict__ bv,
         const float* __restrict__ Wi, const float* __restrict__ bi,
         const float* __restrict__ Wih_d, const float* __restrict__ Whh_d,
         const float* __restrict__ bih_d, const float* __restrict__ bhh_d,
         const float* __restrict__ Wo, const float* __restrict__ bo,
         float* __restrict__ out_xhat, float* __restrict__ out_mean,
         float* __restrict__ out_lv)
{
    extern __shared__ float smem[];
    float* Ws   = smem + WS_OFF;
    float* As   = smem + AS_OFF;
    float* Xs   = smem + XS_OFF;
    float* bsum = smem + BSUM_OFF;

    const int tid = threadIdx.x;
    const int bid = blockIdx.x;
    const int j0  = (bid >> 1) * 8;
    const int m0  = (bid & 1) * 64;
    const int half = m0 >> 6;
    const int gwarp = bid * NWARP + (tid >> 5);
    const int lane  = tid & 31;
    const unsigned mb_blk = smem_u32(smem) + MBAR_BYTE;

    if (tid == 0) {
#pragma unroll
        for (int i = 0; i < 6; ++i) mbar_init(mb_blk + i * 8, 1);
    }
    int barid = 0;
    if (bid == 0 && tid == 0) atomicExch(&g_bar[NBAR - 1], 0u);

    float c_reg[4];
    int ring = 0;

    // ===== pre-phase: weights, zero h tiles, tile seq into blocked layout =====
    load_weights(Ws, bsum, Wih_e, Whh_e, bih_e, bhh_e, j0, tid);
    {
        int gt = bid * NTHR + tid;                  // 0..49151
        for (int idx = gt; idx < 2 * 8 * 4096; idx += NBLK * NTHR)
            g_hT[idx] = 0.0f;                       // buf0, both halves
        // re-tile seq: 2^20 float4 items
        for (int it = gt; it < (1 << 20); it += NBLK * NTHR) {
            int i4 = it & 15;
            int m  = (it >> 4) & 63;
            int t  = (it >> 10) & 511;
            int hf = it >> 19;
            float4 v = *(const float4*)(seq + (((hf * 64 + m) * 512 + t) * 64 + i4 * 4));
            *(float4*)(g_seqblk + (hf * 512 + t) * 4096 + m * 64 + rotc(m, i4 * 4)) = v;
        }
#pragma unroll
        for (int i = 0; i < 4; ++i) c_reg[i] = 0.0f;
    }
    grid_bar(barid++, tid, bid);

    // ===== encoder =====
    for (int t = 0; t < T_; ++t) {
        const float* xt  = g_seqblk + (half * 512 + t) * 4096;
        const float* hTr = g_hT + ((t & 1) * 2 + half) * 32768;
        float*       hTw = g_hT + ((((t + 1) & 1) * 2) + half) * 32768;
        gemm_cell_step(xt, hTr, hTw, g_hflat,
                       Ws, As, Xs, bsum, mb_blk, ring, c_reg, m0, j0, tid);
        grid_bar(barid++, tid, bid);
    }
    // h_n flat in g_hflat; blocked in buf 0

    // ===== VAE =====
    {
        const float* hn = g_hflat;
        for (int idx = gwarp; idx < B_ * L_; idx += NBLK * NWARP) {
            int b = idx >> 6, l = idx & 63;
            const float* hb = hn + b * H_;
            const float* wm = Wm + l * H_;
            const float* wv = Wv + l * H_;
            float sm = 0.0f, sv = 0.0f;
#pragma unroll 4
            for (int k = lane; k < H_; k += 32) {
                float hv = hb[k];
                sm += hv * wm[k];
                sv += hv * wv[k];
            }
#pragma unroll
            for (int off = 16; off > 0; off >>= 1) {
                sm += __shfl_down_sync(0xffffffffu, sm, off);
                sv += __shfl_down_sync(0xffffffffu, sv, off);
            }
            if (lane == 0) {
                sm += bm[l];
                sv += bv[l];
                out_mean[b * L_ + l] = sm;
                out_lv  [b * L_ + l] = sv;
                g_z[b * L_ + l] = sm + eps[b * L_ + l] * expf(0.5f * sv);
            }
        }
    }
    grid_bar(barid++, tid, bid);

    // ===== decoder init =====
    load_weights(Ws, bsum, Wih_d, Whh_d, bih_d, bhh_d, j0, tid);
    {
        int gt = bid * NTHR + tid;
        for (int idx = gt; idx < B_ * H_; idx += NBLK * NTHR) {
            int b = idx >> 9, j = idx & 511;
            const float* zb = g_z + b * L_;
            const float* wr = Wi + j * L_;
            float s = bi[j];
#pragma unroll 16
            for (int k = 0; k < L_; ++k) s += zb[k] * wr[k];
            // write blocked h0 into buf 0
            int hf = b >> 6, m = b & 63, cH = j >> 6, jc = j & 63;
            g_hT[hf * 32768 + (cH * 64 + m) * 64 + rotc(m, jc)] = s;
        }
        for (int idx = gt; idx < 2 * 4096; idx += NBLK * NTHR)
            g_xblk[idx] = 0.0f;
#pragma unroll
        for (int i = 0; i < 4; ++i) c_reg[i] = 0.0f;
    }
    grid_bar(barid++, tid, bid);

    // ===== decoder loop =====
    for (int s = 0; s < DEC_; ++s) {
        const float* xt  = g_xblk + half * 4096;
        const float* hTr = g_hT + ((s & 1) * 2 + half) * 32768;
        float*       hTw = g_hT + ((((s + 1) & 1) * 2) + half) * 32768;
        gemm_cell_step(xt, hTr, hTw, g_hflat,
                       Ws, As, Xs, bsum, mb_blk, ring, c_reg, m0, j0, tid);
        grid_bar(barid++, tid, bid);

        for (int idx = gwarp; idx < B_ * I_; idx += NBLK * NWARP) {
            int b = idx >> 6, i = idx & 63;
            const float* hb = g_hflat + b * H_;
            const float* wr = Wo + i * H_;
            float sum = 0.0f;
#pragma unroll 4
            for (int k = lane; k < H_; k += 32) sum += hb[k] * wr[k];
#pragma unroll
            for (int off = 16; off > 0; off >>= 1)
                sum += __shfl_down_sync(0xffffffffu, sum, off);
            if (lane == 0) {
                float v = sum + bo[i];
                int hf = b >> 6, m = b & 63;
                g_xblk[hf * 4096 + m * 64 + rotc(m, i)] = v;
                out_xhat[(b * DEC_ + s) * I_ + i] = v;
            }
        }
        grid_bar(barid++, tid, bid);
    }
}

// ---------------- launch ----------------
extern "C" void kernel_launch(void* const* d_in, const int* in_sizes, int n_in,
                              void* d_out, int out_size)
{
    (void)in_sizes; (void)n_in; (void)out_size;

    const float* seq    = (const float*)d_in[0];
    const float* eps    = (const float*)d_in[2];
    const float* Wih_e  = (const float*)d_in[3];
    const float* Whh_e  = (const float*)d_in[4];
    const float* bih_e  = (const float*)d_in[5];
    const float* bhh_e  = (const float*)d_in[6];
    const float* Wm     = (const float*)d_in[7];
    const float* bm     = (const float*)d_in[8];
    const float* Wv     = (const float*)d_in[9];
    const float* bv     = (const float*)d_in[10];
    const float* Wi     = (const float*)d_in[11];
    const float* bi     = (const float*)d_in[12];
    const float* Wih_d  = (const float*)d_in[13];
    const float* Whh_d  = (const float*)d_in[14];
    const float* bih_d  = (const float*)d_in[15];
    const float* bhh_d  = (const float*)d_in[16];
    const float* Wo     = (const float*)d_in[17];
    const float* bo     = (const float*)d_in[18];

    float* out      = (float*)d_out;
    float* out_xhat = out;
    float* out_mean = out + B_ * DEC_ * I_;
    float* out_lv   = out_mean + B_ * L_;

    cudaFuncSetAttribute(vae_mega, cudaFuncAttributeMaxDynamicSharedMemorySize,
                         SMEM_BYTES);

    vae_mega<<<NBLK, NTHR, SMEM_BYTES>>>(
        seq, eps,
        Wih_e, Whh_e, bih_e, bhh_e,
        Wm, bm, Wv, bv, Wi, bi,
        Wih_d, Whh_d, bih_d, bhh_d,
        Wo, bo,
        out_xhat, out_mean, out_lv);
}

// round 17
// speedup vs baseline: 1.6505x; 1.4959x over previous
#include <cuda_runtime.h>
#include <cuda_bf16.h>
#include <stdint.h>
#include <math.h>

#define B_   128
#define T_   512
#define I_   64
#define H_   512
#define L_   64
#define DEC_ 100

typedef unsigned long long ull;
typedef unsigned short u16;
typedef unsigned u32;

#define NBLK   128
#define NTHR   256
#define NWARP  8
#define NBAR   715

// ---------------- device globals ----------------
__device__ unsigned g_bar[1024];
// h tiles: [buf 2][half 2][chunk 8] x (hi 8KB | lo 8KB), XOR-swizzled [64m x 64k] bf16
__device__ __align__(16) char g_hb[2 * 2 * 8 * 16384];
// seq tiles: [half 2][t 512] x 16KB
__device__ __align__(16) char g_seqb[2 * 512 * 16384];
// decoder x tiles: [half 2] x 16KB
__device__ __align__(16) char g_xb[2 * 16384];
__device__ __align__(16) float g_hflat[B_ * H_];
__device__ __align__(16) float g_z[B_ * L_];

__device__ __forceinline__ float sigf(float v) { return 1.0f / (1.0f + expf(-v)); }

__device__ __forceinline__ unsigned smem_u32(const void* p) {
    return (unsigned)__cvta_generic_to_shared(p);
}
__device__ __forceinline__ void bf16split(float x, u16& h, u16& l) {
    __nv_bfloat16 bh = __float2bfloat16(x);
    __nv_bfloat16 bl = __float2bfloat16(x - __bfloat162float(bh));
    h = __bfloat16_as_ushort(bh);
    l = __bfloat16_as_ushort(bl);
}

// ---------------- mbarrier / bulk helpers (compiled OK on this harness before) ----
__device__ __forceinline__ void mbar_init(unsigned a, unsigned cnt) {
    asm volatile("mbarrier.init.shared.b64 [%0], %1;" :: "r"(a), "r"(cnt) : "memory");
}
__device__ __forceinline__ void bulk_ld(unsigned dst, const void* src, unsigned bytes, unsigned mbar) {
    asm volatile("mbarrier.arrive.expect_tx.shared.b64 _, [%0], %1;"
                 :: "r"(mbar), "r"(bytes) : "memory");
    asm volatile("cp.async.bulk.shared::cluster.global.mbarrier::complete_tx::bytes "
                 "[%0], [%1], %2, [%3];"
                 :: "r"(dst), "l"(src), "r"(bytes), "r"(mbar) : "memory");
}
__device__ __forceinline__ void mbar_wait(unsigned mbar, unsigned ph) {
    unsigned done;
    asm volatile("{\n\t.reg .pred p;\n\t"
                 "mbarrier.try_wait.parity.acquire.cta.shared::cta.b64 p, [%1], %2;\n\t"
                 "selp.b32 %0, 1, 0, p;\n\t}"
                 : "=r"(done) : "r"(mbar), "r"(ph) : "memory");
    if (!done) {
        asm volatile("{\n\t.reg .pred P1;\n"
                     "WL_%=:\n\t"
                     "mbarrier.try_wait.parity.acquire.cta.shared::cta.b64 P1, [%0], %1, 0x989680;\n\t"
                     "@P1 bra.uni WD_%=;\n\t"
                     "bra.uni WL_%=;\n"
                     "WD_%=:\n\t}" :: "r"(mbar), "r"(ph) : "memory");
    }
}

// ---------------- warp MMA helpers (PTX sm_80+, no 'a' gate) ----------------
__device__ __forceinline__ void ldsm4(u32& r0, u32& r1, u32& r2, u32& r3, unsigned a) {
    asm volatile("ldmatrix.sync.aligned.m8n8.x4.shared.b16 {%0,%1,%2,%3}, [%4];"
                 : "=r"(r0), "=r"(r1), "=r"(r2), "=r"(r3) : "r"(a));
}
__device__ __forceinline__ void mma_bf16(float* d, const u32* a, u32 b0, u32 b1) {
    asm volatile("mma.sync.aligned.m16n8k16.row.col.f32.bf16.bf16.f32 "
                 "{%0,%1,%2,%3}, {%4,%5,%6,%7}, {%8,%9}, {%0,%1,%2,%3};"
                 : "+f"(d[0]), "+f"(d[1]), "+f"(d[2]), "+f"(d[3])
                 : "r"(a[0]), "r"(a[1]), "r"(a[2]), "r"(a[3]), "r"(b0), "r"(b1));
}

// ---------------- software grid barrier (128 co-resident blocks) ----------------
__device__ __forceinline__ void grid_bar(int idx, int tid, int bid)
{
    __threadfence();
    __syncthreads();
    if (tid == 0) {
        atomicAdd(&g_bar[idx], 1u);
        volatile unsigned* p = &g_bar[idx];
        while (*p < (unsigned)NBLK) {}
        __threadfence();
        if (bid == 0 && idx > 0) atomicExch(&g_bar[idx - 1], 0u);
    }
    __syncthreads();
}

// ---------------- smem layout (bytes) ----------------
// Whi/Wlo: [32 n][584 k] bf16, stride 1168B (73x16B, odd -> conflict-free LDSM)
// ABUF: 4 ring buffers x 16KB (hi 8KB | lo 8KB per [64x64] tile)
// Cs: [64][33] f32; bsum 32 f32; 4 mbars
#define WHI_OFF  0
#define WLO_OFF  37376
#define ABUF_OFF 74752
#define CS_OFF   140288
#define BSUM_OFF 148736
#define MB_OFF   148864
#define SMEM_BYTES 148992

// A/h/x tile swizzle: elem (m, k) -> m*128 + (((k>>3)^(m&7))<<4) + (k&7)*2  (per hi/lo 8KB)
__device__ __forceinline__ unsigned tswz(int m, int k) {
    return (unsigned)(m * 128 + ((((k >> 3) ^ (m & 7)) & 7) << 4) + ((k & 7) << 1));
}

// ---------------- resident weight loader -> bf16 hi/lo rows ----------------
__device__ __forceinline__ void load_weights(char* sm, float* bsum,
    const float* __restrict__ Wih, const float* __restrict__ Whh,
    const float* __restrict__ bih, const float* __restrict__ bhh,
    int j0, int tid)
{
    __syncthreads();
    // items: r (32 rows) x kg (72 groups of 8 k)
    for (int q = tid; q < 32 * 72; q += NTHR) {
        int kg = q % 72, r = q / 72;
        int row = (r >> 3) * H_ + j0 + (r & 7);
        const float* src = (kg < 8) ? (Wih + row * I_ + kg * 8)
                                    : (Whh + row * H_ + (kg - 8) * 8);
        float4 v0 = *(const float4*)src;
        float4 v1 = *(const float4*)(src + 4);
        float e[8] = {v0.x, v0.y, v0.z, v0.w, v1.x, v1.y, v1.z, v1.w};
        u16 hi[8], lo[8];
#pragma unroll
        for (int k = 0; k < 8; ++k) bf16split(e[k], hi[k], lo[k]);
        uint4 uh, ul;
        uh.x = hi[0] | (hi[1] << 16); uh.y = hi[2] | (hi[3] << 16);
        uh.z = hi[4] | (hi[5] << 16); uh.w = hi[6] | (hi[7] << 16);
        ul.x = lo[0] | (lo[1] << 16); ul.y = lo[2] | (lo[3] << 16);
        ul.z = lo[4] | (lo[5] << 16); ul.w = lo[6] | (lo[7] << 16);
        *(uint4*)(sm + WHI_OFF + r * 1168 + kg * 16) = uh;
        *(uint4*)(sm + WLO_OFF + r * 1168 + kg * 16) = ul;
    }
    if (tid < 32) {
        int g = tid >> 3, jj = tid & 7;
        bsum[tid] = bih[g * H_ + j0 + jj] + bhh[g * H_ + j0 + jj];
    }
    __syncthreads();
}

// ---------------- fused HMMA LSTM step ----------------
// Block tile [64 m x 32 gatecols]. Warp w: m-tile = w>>1 (16 rows), n-half = w&1 (16 cols).
__device__ __forceinline__ void gemm_cell_step(
    const char* __restrict__ xt,        // 16KB x tile (chunk 0)
    const char* __restrict__ hbr,       // 8 x 16KB h tiles (read)
    char* __restrict__ hbw,             // h tiles (write)
    float* __restrict__ hflat,
    char* sm, float* Cs, const float* bsum,
    unsigned mb, int& ring,
    float* c_reg, int m0, int j0, int tid)
{
    const int w    = tid >> 5;
    const int lane = tid & 31;
    const int mt   = w >> 1;
    const int n0w  = (w & 1) * 16;
    const unsigned abuf_sa = smem_u32(sm + ABUF_OFF);
    const int base = ring;

    // fragment addressing (canonical m16n8k16 row.col)
    const int arow = mt * 16 + (lane & 15);
    const int aun  = lane >> 4;                               // 0/1 -> k+0 / k+8
    const int brow = n0w + (lane & 7) + ((lane >> 4) << 3);   // lanes16-31 -> +8 rows
    const int bk8  = ((lane >> 3) & 1) * 8;
    const unsigned whi_a = smem_u32(sm + WHI_OFF) + brow * 1168;
    const unsigned wlo_a = smem_u32(sm + WLO_OFF) + brow * 1168;
    const unsigned arow_off = (unsigned)(arow * 128);
    const int amask = arow & 7;

    float d0[4] = {0.f, 0.f, 0.f, 0.f};
    float d1[4] = {0.f, 0.f, 0.f, 0.f};

    if (tid == 0) {
        asm volatile("fence.proxy.async;" ::: "memory");
#pragma unroll
        for (int c = 0; c < 4; ++c) {
            int f = base + c;
            const char* src = (c == 0) ? xt : hbr + (c - 1) * 16384;
            bulk_ld(abuf_sa + (f & 3) * 16384, src, 16384u, mb + (f & 3) * 8);
        }
    }

    for (int c = 0; c < 9; ++c) {
        const int f = base + c;
        mbar_wait(mb + (f & 3) * 8, (f >> 2) & 1);
        const unsigned ta = abuf_sa + (f & 3) * 16384;
        const int kb = c * 64;
#pragma unroll
        for (int ks = 0; ks < 4; ++ks) {
            unsigned aoff = arow_off + (unsigned)(((((ks << 1) | aun) ^ amask) & 7) << 4);
            u32 ah[4], al[4], bh[4], bl[4];
            ldsm4(ah[0], ah[1], ah[2], ah[3], ta + aoff);
            ldsm4(al[0], al[1], al[2], al[3], ta + 8192 + aoff);
            unsigned bko = (unsigned)((kb + ks * 16 + bk8) * 2);
            ldsm4(bh[0], bh[1], bh[2], bh[3], whi_a + bko);
            ldsm4(bl[0], bl[1], bl[2], bl[3], wlo_a + bko);
            mma_bf16(d0, ah, bh[0], bh[1]);
            mma_bf16(d0, ah, bl[0], bl[1]);
            mma_bf16(d0, al, bh[0], bh[1]);
            mma_bf16(d1, ah, bh[2], bh[3]);
            mma_bf16(d1, ah, bl[2], bl[3]);
            mma_bf16(d1, al, bh[2], bh[3]);
        }
        __syncthreads();                    // buffer f drained by all warps
        if (tid == 0 && c + 4 < 9) {
            int f2 = base + c + 4;
            bulk_ld(abuf_sa + (f2 & 3) * 16384, hbr + (c + 3) * 16384, 16384u,
                    mb + (f2 & 3) * 8);
        }
    }
    ring += 9;

    // stage fragments into Cs[64][33]
    {
        int rl = lane >> 2, cb = (lane & 3) * 2;
        int r0g = mt * 16 + rl;
        Cs[r0g * 33 + n0w + cb]           = d0[0];
        Cs[r0g * 33 + n0w + cb + 1]       = d0[1];
        Cs[(r0g + 8) * 33 + n0w + cb]     = d0[2];
        Cs[(r0g + 8) * 33 + n0w + cb + 1] = d0[3];
        Cs[r0g * 33 + n0w + 8 + cb]           = d1[0];
        Cs[r0g * 33 + n0w + 8 + cb + 1]       = d1[1];
        Cs[(r0g + 8) * 33 + n0w + 8 + cb]     = d1[2];
        Cs[(r0g + 8) * 33 + n0w + 8 + cb + 1] = d1[3];
    }
    __syncthreads();

    // cell update: 512 cells, 2 per thread
    const int cH = j0 >> 6;
#pragma unroll
    for (int q = 0; q < 2; ++q) {
        int idx = q * NTHR + tid;
        int m = idx >> 3, jj = idx & 7;
        float gi = Cs[m * 33 + jj]      + bsum[jj];
        float gf = Cs[m * 33 + 8 + jj]  + bsum[8 + jj];
        float gg = Cs[m * 33 + 16 + jj] + bsum[16 + jj];
        float go = Cs[m * 33 + 24 + jj] + bsum[24 + jj];
        float cn = sigf(gf) * c_reg[q] + sigf(gi) * tanhf(gg);
        float hn = sigf(go) * tanhf(cn);
        c_reg[q] = cn;
        hflat[(m0 + m) * H_ + j0 + jj] = hn;
        u16 hh, hl;
        bf16split(hn, hh, hl);
        int kcol = (j0 & 63) + jj;
        unsigned off = tswz(m, kcol);
        *(u16*)(hbw + cH * 16384 + off)        = hh;
        *(u16*)(hbw + cH * 16384 + 8192 + off) = hl;
    }
    __syncthreads();
}

// ---------------- the megakernel ----------------
__global__ void __launch_bounds__(NTHR, 1)
vae_mega(const float* __restrict__ seq,  const float* __restrict__ eps,
         const float* __restrict__ Wih_e, const float* __restrict__ Whh_e,
         const float* __restrict__ bih_e, const float* __restrict__ bhh_e,
         const float* __restrict__ Wm, const float* __restrict__ bm,
         const float* __restrict__ Wv, const float* __restrict__ bv,
         const float* __restrict__ Wi, const float* __restrict__ bi,
         const float* __restrict__ Wih_d, const float* __restrict__ Whh_d,
         const float* __restrict__ bih_d, const float* __restrict__ bhh_d,
         const float* __restrict__ Wo, const float* __restrict__ bo,
         float* __restrict__ out_xhat, float* __restrict__ out_mean,
         float* __restrict__ out_lv)
{
    extern __shared__ char sm[];
    float* Cs   = (float*)(sm + CS_OFF);
    float* bsum = (float*)(sm + BSUM_OFF);
    const unsigned mb = smem_u32(sm + MB_OFF);

    const int tid = threadIdx.x;
    const int bid = blockIdx.x;
    const int j0  = (bid >> 1) * 8;
    const int m0  = (bid & 1) * 64;
    const int half = bid & 1;
    const int gwarp = bid * NWARP + (tid >> 5);   // 0..1023
    const int lane  = tid & 31;

    if (tid == 0) {
#pragma unroll
        for (int i = 0; i < 4; ++i) mbar_init(mb + i * 8, 1);
    }
    __syncthreads();

    int barid = 0;
    if (bid == 0 && tid == 0) atomicExch(&g_bar[NBAR - 1], 0u);

    float c_reg[2];
    int ring = 0;

    // ===== pre-phase: weights, zero h buf0 + x tiles, pre-tile seq =====
    load_weights(sm, bsum, Wih_e, Whh_e, bih_e, bhh_e, j0, tid);
    {
        int gt = bid * NTHR + tid;                  // 0..32767
        for (int idx = gt; idx < 2 * 8 * 16384 / 4; idx += NBLK * NTHR)
            ((int*)g_hb)[idx] = 0;                  // buf0, both halves
        for (int idx = gt; idx < 2 * 16384 / 4; idx += NBLK * NTHR)
            ((int*)g_xb)[idx] = 0;
        // seq -> tiles: items (half, t, m, kg)
        for (int q = gt; q < 2 * 512 * 64 * 8; q += NBLK * NTHR) {
            int kg = q & 7, m = (q >> 3) & 63, t = (q >> 9) & 511, hf = q >> 18;
            const float* src = seq + ((hf * 64 + m) * 512 + t) * 64 + kg * 8;
            float4 v0 = *(const float4*)src;
            float4 v1 = *(const float4*)(src + 4);
            float e[8] = {v0.x, v0.y, v0.z, v0.w, v1.x, v1.y, v1.z, v1.w};
            u16 hi[8], lo[8];
#pragma unroll
            for (int k = 0; k < 8; ++k) bf16split(e[k], hi[k], lo[k]);
            uint4 uh, ul;
            uh.x = hi[0] | (hi[1] << 16); uh.y = hi[2] | (hi[3] << 16);
            uh.z = hi[4] | (hi[5] << 16); uh.w = hi[6] | (hi[7] << 16);
            ul.x = lo[0] | (lo[1] << 16); ul.y = lo[2] | (lo[3] << 16);
            ul.z = lo[4] | (lo[5] << 16); ul.w = lo[6] | (lo[7] << 16);
            char* dst = g_seqb + (hf * 512 + t) * 16384;
            unsigned off = (unsigned)(m * 128 + (((kg ^ (m & 7)) & 7) << 4));
            *(uint4*)(dst + off)        = uh;
            *(uint4*)(dst + 8192 + off) = ul;
        }
        c_reg[0] = 0.0f; c_reg[1] = 0.0f;
    }
    grid_bar(barid++, tid, bid);

    // ===== encoder =====
    for (int t = 0; t < T_; ++t) {
        gemm_cell_step(g_seqb + (half * 512 + t) * 16384,
                       g_hb + ((t & 1) * 2 + half) * 8 * 16384,
                       g_hb + (((t + 1) & 1) * 2 + half) * 8 * 16384,
                       g_hflat, sm, Cs, bsum, mb, ring, c_reg, m0, j0, tid);
        grid_bar(barid++, tid, bid);
    }

    // ===== VAE =====
    {
        const float* hn = g_hflat;
        for (int idx = gwarp; idx < B_ * L_; idx += NBLK * NWARP) {
            int b = idx >> 6, l = idx & 63;
            const float* hb = hn + b * H_;
            const float* wm = Wm + l * H_;
            const float* wv = Wv + l * H_;
            float sm_ = 0.0f, sv = 0.0f;
#pragma unroll 4
            for (int k = lane; k < H_; k += 32) {
                float hv = hb[k];
                sm_ += hv * wm[k];
                sv  += hv * wv[k];
            }
#pragma unroll
            for (int off = 16; off > 0; off >>= 1) {
                sm_ += __shfl_down_sync(0xffffffffu, sm_, off);
                sv  += __shfl_down_sync(0xffffffffu, sv, off);
            }
            if (lane == 0) {
                sm_ += bm[l];
                sv  += bv[l];
                out_mean[b * L_ + l] = sm_;
                out_lv  [b * L_ + l] = sv;
                g_z[b * L_ + l] = sm_ + eps[b * L_ + l] * expf(0.5f * sv);
            }
        }
    }
    grid_bar(barid++, tid, bid);

    // ===== decoder init =====
    load_weights(sm, bsum, Wih_d, Whh_d, bih_d, bhh_d, j0, tid);
    {
        int gt = bid * NTHR + tid;
        for (int idx = gt; idx < B_ * H_; idx += NBLK * NTHR) {
            int b = idx >> 9, j = idx & 511;
            const float* zb = g_z + b * L_;
            const float* wr = Wi + j * L_;
            float s = bi[j];
#pragma unroll 16
            for (int k = 0; k < L_; ++k) s += zb[k] * wr[k];
            g_hflat[b * H_ + j] = s;
            u16 hh, hl;
            bf16split(s, hh, hl);
            char* dst = g_hb + ((b >> 6)) * 8 * 16384 + (j >> 6) * 16384;  // buf0
            unsigned off = tswz(b & 63, j & 63);
            *(u16*)(dst + off)        = hh;
            *(u16*)(dst + 8192 + off) = hl;
        }
        for (int idx = gt; idx < 2 * 16384 / 4; idx += NBLK * NTHR)
            ((int*)g_xb)[idx] = 0;
        c_reg[0] = 0.0f; c_reg[1] = 0.0f;
    }
    grid_bar(barid++, tid, bid);

    // ===== decoder loop =====
    for (int s = 0; s < DEC_; ++s) {
        gemm_cell_step(g_xb + half * 16384,
                       g_hb + ((s & 1) * 2 + half) * 8 * 16384,
                       g_hb + (((s + 1) & 1) * 2 + half) * 8 * 16384,
                       g_hflat, sm, Cs, bsum, mb, ring, c_reg, m0, j0, tid);
        grid_bar(barid++, tid, bid);

        for (int idx = gwarp; idx < B_ * I_; idx += NBLK * NWARP) {
            int b = idx >> 6, i = idx & 63;
            const float* hb = g_hflat + b * H_;
            const float* wr = Wo + i * H_;
            float sum = 0.0f;
#pragma unroll 4
            for (int k = lane; k < H_; k += 32) sum += hb[k] * wr[k];
#pragma unroll
            for (int off = 16; off > 0; off >>= 1)
                sum += __shfl_down_sync(0xffffffffu, sum, off);
            if (lane == 0) {
                float v = sum + bo[i];
                u16 hh, hl;
                bf16split(v, hh, hl);
                char* dst = g_xb + (b >> 6) * 16384;
                unsigned off2 = tswz(b & 63, i);
                *(u16*)(dst + off2)        = hh;
                *(u16*)(dst + 8192 + off2) = hl;
                out_xhat[(b * DEC_ + s) * I_ + i] = v;
            }
        }
        grid_bar(barid++, tid, bid);
    }
}

// ---------------- launch ----------------
extern "C" void kernel_launch(void* const* d_in, const int* in_sizes, int n_in,
                              void* d_out, int out_size)
{
    (void)in_sizes; (void)n_in; (void)out_size;

    const float* seq    = (const float*)d_in[0];
    const float* eps    = (const float*)d_in[2];
    const float* Wih_e  = (const float*)d_in[3];
    const float* Whh_e  = (const float*)d_in[4];
    const float* bih_e  = (const float*)d_in[5];
    const float* bhh_e  = (const float*)d_in[6];
    const float* Wm     = (const float*)d_in[7];
    const float* bm     = (const float*)d_in[8];
    const float* Wv     = (const float*)d_in[9];
    const float* bv     = (const float*)d_in[10];
    const float* Wi     = (const float*)d_in[11];
    const float* bi     = (const float*)d_in[12];
    const float* Wih_d  = (const float*)d_in[13];
    const float* Whh_d  = (const float*)d_in[14];
    const float* bih_d  = (const float*)d_in[15];
    const float* bhh_d  = (const float*)d_in[16];
    const float* Wo     = (const float*)d_in[17];
    const float* bo     = (const float*)d_in[18];

    float* out      = (float*)d_out;
    float* out_xhat = out;
    float* out_mean = out + B_ * DEC_ * I_;
    float* out_lv   = out_mean + B_ * L_;

    cudaFuncSetAttribute(vae_mega, cudaFuncAttributeMaxDynamicSharedMemorySize,
                         SMEM_BYTES);

    vae_mega<<<NBLK, NTHR, SMEM_BYTES>>>(
        seq, eps,
        Wih_e, Whh_e, bih_e, bhh_e,
        Wm, bm, Wv, bv, Wi, bi,
        Wih_d, Whh_d, bih_d, bhh_d,
        Wo, bo,
        out_xhat, out_mean, out_lv);
}